// round 2
// baseline (speedup 1.0000x reference)
#include <cuda_runtime.h>

// SupervisedContrastiveLoss on GB300 (sm_103a)
//   h = x / max(||x||, 1e-12)
//   neg_sum[i] = sum_{lab_j != lab_i} exp(<h_i,h_j>/T)                       (pass 1)
//   row_sum[i] = sum_{lab_j == lab_i, j != i} log(1 + neg_sum[i]*exp(-s/T))  (pass 2)
//   pos_cnt[i] counted directly in pass 2
//   out = mean_i over {pos_cnt>0} of row_sum[i]/pos_cnt[i]
// Symmetric tiling: only tiles bj >= bi computed; off-diagonal tiles feed both
// row-side (i) and column-side (j) accumulators.

#define NMAX 8192
#define D    256
#define INV_T 14.285714285714285714f   // 1/0.07

__device__ float g_Hn[NMAX * D];
__device__ float g_neg[NMAX];
__device__ float g_row[NMAX];
__device__ float g_cnt[NMAX];
__device__ int   g_lab[NMAX];

// ---------------------------------------------------------------------------
// Label ingest, robust to int32 vs int64 storage. View buffer as u32 words.
// int64 layout with small non-negative values => all odd words (high halves)
// are zero. Detection touches only the first N words (in-bounds either way).
// Equality-based masks only need a consistent per-row integer code.
// ---------------------------------------------------------------------------
__global__ void lab_kernel(const unsigned int* __restrict__ v, int N)
{
    __shared__ int s_or[1024];
    int tid = threadIdx.x;
    unsigned int o = 0;
    for (int i = 2 * tid + 1; i < N; i += 2048) o |= v[i];
    s_or[tid] = (o != 0);
    __syncthreads();
    for (int s = 512; s; s >>= 1) { if (tid < s) s_or[tid] |= s_or[tid + s]; __syncthreads(); }
    int is32 = s_or[0];
    for (int i = tid; i < N; i += 1024)
        g_lab[i] = is32 ? (int)v[i] : (int)v[2 * i];
}

// ---------------------------------------------------------------------------
// Normalize: one warp per row; zero per-row accumulators.
// ---------------------------------------------------------------------------
__global__ void norm_kernel(const float* __restrict__ x, int N)
{
    int row  = blockIdx.x;
    if (row >= N) return;
    int lane = threadIdx.x;

    const float4* x4 = reinterpret_cast<const float4*>(x + (size_t)row * D);
    float4 a = x4[lane];
    float4 b = x4[lane + 32];

    float ss = a.x*a.x + a.y*a.y + a.z*a.z + a.w*a.w
             + b.x*b.x + b.y*b.y + b.z*b.z + b.w*b.w;
#pragma unroll
    for (int o = 16; o; o >>= 1) ss += __shfl_xor_sync(0xffffffffu, ss, o);

    float inv = 1.0f / fmaxf(sqrtf(ss), 1e-12f);
    a.x *= inv; a.y *= inv; a.z *= inv; a.w *= inv;
    b.x *= inv; b.y *= inv; b.z *= inv; b.w *= inv;

    float4* h4 = reinterpret_cast<float4*>(g_Hn + (size_t)row * D);
    h4[lane]      = a;
    h4[lane + 32] = b;

    if (lane == 0) { g_neg[row] = 0.0f; g_row[row] = 0.0f; g_cnt[row] = 0.0f; }
}

// ---------------------------------------------------------------------------
// Symmetric pass kernels: BM=BN=64, BK=16, 256 threads, 4x4 microtile.
// ---------------------------------------------------------------------------
__global__ __launch_bounds__(256) void pass1_kernel(int N)
{
    int bi = blockIdx.y, bj = blockIdx.x;
    if (bj < bi) return;

    __shared__ float As[64][17];
    __shared__ float Bs[64][17];
    __shared__ int   labA[64], labB[64];
    __shared__ float colsum[64];

    int tid = threadIdx.x;
    int tx  = tid & 15;
    int ty  = tid >> 4;
    int i0  = bi * 64, j0 = bj * 64;
    bool offdiag = (bi != bj);

    if (tid < 64) {
        labA[tid]   = g_lab[i0 + tid];
        labB[tid]   = g_lab[j0 + tid];
        colsum[tid] = 0.0f;
    }

    float acc[4][4];
#pragma unroll
    for (int u = 0; u < 4; u++)
#pragma unroll
        for (int v = 0; v < 4; v++) acc[u][v] = 0.0f;

    int lr = tid >> 2;
    int lc = (tid & 3) * 4;

    for (int k0 = 0; k0 < D; k0 += 16) {
        float4 av = *reinterpret_cast<const float4*>(&g_Hn[(size_t)(i0 + lr) * D + k0 + lc]);
        float4 bv = *reinterpret_cast<const float4*>(&g_Hn[(size_t)(j0 + lr) * D + k0 + lc]);
        __syncthreads();
        As[lr][lc+0] = av.x; As[lr][lc+1] = av.y; As[lr][lc+2] = av.z; As[lr][lc+3] = av.w;
        Bs[lr][lc+0] = bv.x; Bs[lr][lc+1] = bv.y; Bs[lr][lc+2] = bv.z; Bs[lr][lc+3] = bv.w;
        __syncthreads();
#pragma unroll
        for (int k = 0; k < 16; k++) {
            float a[4], b[4];
#pragma unroll
            for (int u = 0; u < 4; u++) a[u] = As[ty*4 + u][k];
#pragma unroll
            for (int v = 0; v < 4; v++) b[v] = Bs[tx*4 + v][k];
#pragma unroll
            for (int u = 0; u < 4; u++)
#pragma unroll
                for (int v = 0; v < 4; v++) acc[u][v] = fmaf(a[u], b[v], acc[u][v]);
        }
    }

    float rowp[4] = {0,0,0,0}, colp[4] = {0,0,0,0};
#pragma unroll
    for (int u = 0; u < 4; u++) {
        int la = labA[ty*4 + u];
#pragma unroll
        for (int v = 0; v < 4; v++) {
            if (la != labB[tx*4 + v]) {
                float e = expf(acc[u][v] * INV_T);
                rowp[u] += e;
                colp[v] += e;
            }
        }
    }

#pragma unroll
    for (int u = 0; u < 4; u++) {
        float val = rowp[u];
#pragma unroll
        for (int o = 8; o; o >>= 1) val += __shfl_xor_sync(0xffffffffu, val, o);
        if (tx == 0) atomicAdd(&g_neg[i0 + ty*4 + u], val);
    }

    if (offdiag) {
#pragma unroll
        for (int v = 0; v < 4; v++) atomicAdd(&colsum[tx*4 + v], colp[v]);
        __syncthreads();
        if (tid < 64) atomicAdd(&g_neg[j0 + tid], colsum[tid]);
    }
}

__global__ __launch_bounds__(256) void pass2_kernel(int N)
{
    int bi = blockIdx.y, bj = blockIdx.x;
    if (bj < bi) return;

    __shared__ float As[64][17];
    __shared__ float Bs[64][17];
    __shared__ int   labA[64], labB[64];
    __shared__ float negA[64], negB[64];
    __shared__ float colsum[64], colcnt[64];

    int tid = threadIdx.x;
    int tx  = tid & 15;
    int ty  = tid >> 4;
    int i0  = bi * 64, j0 = bj * 64;
    bool offdiag = (bi != bj);

    if (tid < 64) {
        labA[tid]   = g_lab[i0 + tid];
        labB[tid]   = g_lab[j0 + tid];
        negA[tid]   = g_neg[i0 + tid];
        negB[tid]   = g_neg[j0 + tid];
        colsum[tid] = 0.0f;
        colcnt[tid] = 0.0f;
    }

    float acc[4][4];
#pragma unroll
    for (int u = 0; u < 4; u++)
#pragma unroll
        for (int v = 0; v < 4; v++) acc[u][v] = 0.0f;

    int lr = tid >> 2;
    int lc = (tid & 3) * 4;

    for (int k0 = 0; k0 < D; k0 += 16) {
        float4 av = *reinterpret_cast<const float4*>(&g_Hn[(size_t)(i0 + lr) * D + k0 + lc]);
        float4 bv = *reinterpret_cast<const float4*>(&g_Hn[(size_t)(j0 + lr) * D + k0 + lc]);
        __syncthreads();
        As[lr][lc+0] = av.x; As[lr][lc+1] = av.y; As[lr][lc+2] = av.z; As[lr][lc+3] = av.w;
        Bs[lr][lc+0] = bv.x; Bs[lr][lc+1] = bv.y; Bs[lr][lc+2] = bv.z; Bs[lr][lc+3] = bv.w;
        __syncthreads();
#pragma unroll
        for (int k = 0; k < 16; k++) {
            float a[4], b[4];
#pragma unroll
            for (int u = 0; u < 4; u++) a[u] = As[ty*4 + u][k];
#pragma unroll
            for (int v = 0; v < 4; v++) b[v] = Bs[tx*4 + v][k];
#pragma unroll
            for (int u = 0; u < 4; u++)
#pragma unroll
                for (int v = 0; v < 4; v++) acc[u][v] = fmaf(a[u], b[v], acc[u][v]);
        }
    }

    float rowp[4] = {0,0,0,0}, colp[4] = {0,0,0,0};
    float rowc[4] = {0,0,0,0}, colc[4] = {0,0,0,0};
#pragma unroll
    for (int u = 0; u < 4; u++) {
        int la   = labA[ty*4 + u];
        int gi   = i0 + ty*4 + u;
        float na = negA[ty*4 + u];
#pragma unroll
        for (int v = 0; v < 4; v++) {
            int gj = j0 + tx*4 + v;
            if (la == labB[tx*4 + v] && gi != gj) {
                float xm = expf(-acc[u][v] * INV_T);
                rowp[u] += logf(1.0f + na * xm);
                rowc[u] += 1.0f;
                if (offdiag) {
                    colp[v] += logf(1.0f + negB[tx*4 + v] * xm);
                    colc[v] += 1.0f;
                }
            }
        }
    }

#pragma unroll
    for (int u = 0; u < 4; u++) {
        float val = rowp[u];
        float cntv = rowc[u];
#pragma unroll
        for (int o = 8; o; o >>= 1) {
            val  += __shfl_xor_sync(0xffffffffu, val, o);
            cntv += __shfl_xor_sync(0xffffffffu, cntv, o);
        }
        if (tx == 0) {
            atomicAdd(&g_row[i0 + ty*4 + u], val);
            atomicAdd(&g_cnt[i0 + ty*4 + u], cntv);
        }
    }

    if (offdiag) {
#pragma unroll
        for (int v = 0; v < 4; v++) {
            atomicAdd(&colsum[tx*4 + v], colp[v]);
            atomicAdd(&colcnt[tx*4 + v], colc[v]);
        }
        __syncthreads();
        if (tid < 64) {
            atomicAdd(&g_row[j0 + tid], colsum[tid]);
            atomicAdd(&g_cnt[j0 + tid], colcnt[tid]);
        }
    }
}

// ---------------------------------------------------------------------------
// Final reduction with directly-counted pos_cnt.
// ---------------------------------------------------------------------------
__global__ void final_kernel(float* __restrict__ out, int N)
{
    __shared__ float sred[1024];
    __shared__ int   ired[1024];
    int tid = threadIdx.x;

    float sum = 0.0f; int vc = 0;
    for (int i = tid; i < N; i += 1024) {
        float c = g_cnt[i];
        if (c > 0.5f) { sum += g_row[i] / c; vc++; }
    }
    sred[tid] = sum; ired[tid] = vc;
    __syncthreads();
    for (int s = 512; s; s >>= 1) {
        if (tid < s) { sred[tid] += sred[tid + s]; ired[tid] += ired[tid + s]; }
        __syncthreads();
    }
    if (tid == 0) out[0] = (ired[0] > 0) ? sred[0] / (float)ired[0] : 0.0f;
}

// ---------------------------------------------------------------------------
extern "C" void kernel_launch(void* const* d_in, const int* in_sizes, int n_in,
                              void* d_out, int out_size)
{
    const float*        x   = (const float*)d_in[0];
    const unsigned int* lv  = (const unsigned int*)d_in[1];
    float*              out = (float*)d_out;

    int N = in_sizes[1];
    if (N > NMAX) N = NMAX;

    lab_kernel<<<1, 1024>>>(lv, N);
    norm_kernel<<<N, 32>>>(x, N);

    int T = N / 64;
    dim3 grid(T, T);
    pass1_kernel<<<grid, 256>>>(N);
    pass2_kernel<<<grid, 256>>>(N);

    final_kernel<<<1, 1024>>>(out, N);
}

// round 6
// speedup vs baseline: 2.3918x; 2.3918x over previous
#include <cuda_runtime.h>
#include <cuda_bf16.h>
#include <stdint.h>

// SupervisedContrastiveLoss on GB300 (sm_103 target) — mma.sync bf16 split GEMM.
// (Third submission of this candidate: R4/R5 failed in the GPU broker before compile;
//  R3's ptxas error proves the pipeline surfaces kernel-side faults differently.)
//   h = x/||x||; h = hi + lo (bf16 split); s ≈ hi*hi^T + hi*lo^T + lo*hi^T (fp32 accum)
//   pass1: neg_sum[i] = sum_{lab_j != lab_i} exp(s_ij/T)
//   pass2: row_sum[i] = sum_{lab_j==lab_i, j!=i} log(1+neg_sum[i]*exp(-s_ij/T)); pos_cnt counted
//   out = mean over valid rows of row_sum/pos_cnt
// Symmetric: tiles bj >= bi only; off-diag tiles feed row-side and col-side accumulators.

#define NMAX 8192
#define D    256
#define INV_T 14.285714285714285714f

__device__ uint4 g_hi4[NMAX * D * 2 / 16];   // bf16 [NMAX][D]
__device__ uint4 g_lo4[NMAX * D * 2 / 16];
__device__ float g_neg[NMAX];
__device__ float g_row[NMAX];
__device__ float g_cnt[NMAX];
__device__ int   g_lab[NMAX];

// ---------------- PTX helpers (sm_80-era, valid on plain sm_103) ------------
__device__ __forceinline__ uint32_t smem_u32(const void* p) {
    uint32_t a;
    asm("{ .reg .u64 t; cvta.to.shared.u64 t, %1; cvt.u32.u64 %0, t; }" : "=r"(a) : "l"(p));
    return a;
}

#define LDSM_X4(r0,r1,r2,r3,addr) \
    asm volatile("ldmatrix.sync.aligned.m8n8.x4.shared.b16 {%0,%1,%2,%3}, [%4];" \
        : "=r"(r0),"=r"(r1),"=r"(r2),"=r"(r3) : "r"(addr))
#define LDSM_X2(r0,r1,addr) \
    asm volatile("ldmatrix.sync.aligned.m8n8.x2.shared.b16 {%0,%1}, [%2];" \
        : "=r"(r0),"=r"(r1) : "r"(addr))
#define MMA16816(d,a0,a1,a2,a3,b0,b1) \
    asm volatile("mma.sync.aligned.m16n8k16.row.col.f32.bf16.bf16.f32 " \
        "{%0,%1,%2,%3}, {%4,%5,%6,%7}, {%8,%9}, {%0,%1,%2,%3};" \
        : "+f"((d)[0]),"+f"((d)[1]),"+f"((d)[2]),"+f"((d)[3]) \
        : "r"(a0),"r"(a1),"r"(a2),"r"(a3),"r"(b0),"r"(b1))

// -------------------- dynamic SMEM layout (bytes) ---------------------------
#define SM_LABA   0        // int[128]
#define SM_LABB   512
#define SM_NEGA   1024     // float[128]
#define SM_NEGB   1536
#define SM_SROW   2048     // float[128]
#define SM_SCOL   2560
#define SM_SCNR   3072
#define SM_SCNC   3584
#define SM_TILE   4096
#define TSTRIDE   144      // 128B data + 16B pad -> ldmatrix phase covers all 32 banks
#define TBYTES    (128 * TSTRIDE)   // 18432
#define OFF_AHI   (SM_TILE + 0*TBYTES)
#define OFF_ALO   (SM_TILE + 1*TBYTES)
#define OFF_BHI   (SM_TILE + 2*TBYTES)
#define OFF_BLO   (SM_TILE + 3*TBYTES)
#define SMEM_TOTAL (SM_TILE + 4*TBYTES)   // 77824

// ---------------------------------------------------------------------------
// Label ingest, robust to int32 vs int64 storage (equality-only semantics).
// ---------------------------------------------------------------------------
__global__ void lab_kernel(const unsigned int* __restrict__ v, int N)
{
    __shared__ int s_or[1024];
    int tid = threadIdx.x;
    unsigned int o = 0;
    for (int i = 2 * tid + 1; i < N; i += 2048) o |= v[i];
    s_or[tid] = (o != 0);
    __syncthreads();
    for (int s = 512; s; s >>= 1) { if (tid < s) s_or[tid] |= s_or[tid + s]; __syncthreads(); }
    int is32 = s_or[0];
    for (int i = tid; i < N; i += 1024)
        g_lab[i] = is32 ? (int)v[i] : (int)v[2 * i];
}

// ---------------------------------------------------------------------------
// Normalize + bf16 hi/lo split. 256 threads = 8 warps, one warp per row.
// ---------------------------------------------------------------------------
__global__ __launch_bounds__(256) void prep_kernel(const float* __restrict__ x, int N)
{
    int row  = blockIdx.x * 8 + (threadIdx.x >> 5);
    if (row >= N) return;
    int lane = threadIdx.x & 31;

    const float4* x4 = reinterpret_cast<const float4*>(x + (size_t)row * D);
    float4 a = x4[lane];
    float4 b = x4[lane + 32];

    float ss = a.x*a.x + a.y*a.y + a.z*a.z + a.w*a.w
             + b.x*b.x + b.y*b.y + b.z*b.z + b.w*b.w;
#pragma unroll
    for (int o = 16; o; o >>= 1) ss += __shfl_xor_sync(0xffffffffu, ss, o);

    float inv = 1.0f / fmaxf(sqrtf(ss), 1e-12f);
    a.x *= inv; a.y *= inv; a.z *= inv; a.w *= inv;
    b.x *= inv; b.y *= inv; b.z *= inv; b.w *= inv;

    __nv_bfloat162* hi2 = reinterpret_cast<__nv_bfloat162*>(g_hi4);
    __nv_bfloat162* lo2 = reinterpret_cast<__nv_bfloat162*>(g_lo4);
    size_t base = (size_t)row * (D / 2);

    float vals[8] = {a.x, a.y, a.z, a.w, b.x, b.y, b.z, b.w};
#pragma unroll
    for (int p = 0; p < 4; p++) {
        float u = vals[2*p], v = vals[2*p+1];
        __nv_bfloat16 hu = __float2bfloat16(u);
        __nv_bfloat16 hv = __float2bfloat16(v);
        __nv_bfloat162 H; H.x = hu; H.y = hv;
        __nv_bfloat162 L; L.x = __float2bfloat16(u - __bfloat162float(hu));
        L.y = __float2bfloat16(v - __bfloat162float(hv));
        size_t idx2 = base + ((p < 2) ? (lane*2 + p) : (64 + lane*2 + (p-2)));
        hi2[idx2] = H;
        lo2[idx2] = L;
    }

    if (lane == 0) { g_neg[row] = 0.0f; g_row[row] = 0.0f; g_cnt[row] = 0.0f; }
}

// ---------------------------------------------------------------------------
// Pass kernel: 128x128 tile via mma.sync bf16, symmetric upper-triangle grid.
// 8 warps: warp tile 64x32 (wm = wid&1 -> 2 x 64 rows, wn = wid>>1 -> 4 x 32 cols).
// ---------------------------------------------------------------------------
template <int PASS>
__global__ __launch_bounds__(256, 1) void pass_kernel(int N)
{
    extern __shared__ char sm[];
    int bi = blockIdx.y, bj = blockIdx.x;
    if (bj < bi) return;

    int tid  = threadIdx.x;
    int wid  = tid >> 5;
    int lane = tid & 31;
    int i0 = bi * 128, j0 = bj * 128;
    bool offdiag = (bi != bj);
    uint32_t smb = smem_u32(sm);

    int* labA   = (int*)(sm + SM_LABA);
    int* labB   = (int*)(sm + SM_LABB);
    float* negA = (float*)(sm + SM_NEGA);
    float* negB = (float*)(sm + SM_NEGB);
    float* srow = (float*)(sm + SM_SROW);
    float* scol = (float*)(sm + SM_SCOL);
    float* scnr = (float*)(sm + SM_SCNR);
    float* scnc = (float*)(sm + SM_SCNC);

    if (tid < 128) {
        labA[tid] = g_lab[i0 + tid];
        labB[tid] = g_lab[j0 + tid];
        srow[tid] = 0.0f; scol[tid] = 0.0f;
        if (PASS == 2) {
            negA[tid] = g_neg[i0 + tid];
            negB[tid] = g_neg[j0 + tid];
            scnr[tid] = 0.0f; scnc[tid] = 0.0f;
        }
    }

    int wm0 = (wid & 1) * 64;
    int wn0 = (wid >> 1) * 32;

    float acc[4][4][4];
#pragma unroll
    for (int fm = 0; fm < 4; fm++)
#pragma unroll
        for (int fn = 0; fn < 4; fn++)
#pragma unroll
            for (int k = 0; k < 4; k++) acc[fm][fn][k] = 0.0f;

    const char* hi_base = (const char*)g_hi4;
    const char* lo_base = (const char*)g_lo4;

    // fragment smem address components (per-lane constant)
    int a_row = lane & 15;                 // + fm*16 (+wm0)
    int a_kb  = (lane >> 4) * 16;          // + ks*32
    int b_row = lane & 7;                  // + fn*8 (+wn0)
    int b_kb  = ((lane >> 3) & 1) * 16;    // + ks*32

#pragma unroll 1
    for (int kc = 0; kc < 4; kc++) {       // K chunks of 64
        __syncthreads();
        // load 4 tiles: Ahi, Alo, Bhi, Blo — 128 rows x 128B each
#pragma unroll
        for (int t = 0; t < 16; t++) {
            int idx = tid + t * 256;
            int mat = idx >> 10;
            int rem = idx & 1023;
            int row = rem >> 3;
            int c   = rem & 7;
            int grow = (mat < 2) ? (i0 + row) : (j0 + row);
            const char* src = ((mat & 1) ? lo_base : hi_base)
                            + (size_t)grow * 512 + kc * 128 + c * 16;
            uint4 v = *(const uint4*)src;
            *(uint4*)(sm + SM_TILE + mat * TBYTES + row * TSTRIDE + c * 16) = v;
        }
        __syncthreads();

#pragma unroll
        for (int ks = 0; ks < 4; ks++) {   // k16 steps within chunk
            uint32_t ahi[4][4], alo[4][4], bhi[4][2], blo[4][2];
#pragma unroll
            for (int fm = 0; fm < 4; fm++) {
                uint32_t ra = smb + OFF_AHI + (wm0 + fm*16 + a_row) * TSTRIDE + ks*32 + a_kb;
                LDSM_X4(ahi[fm][0], ahi[fm][1], ahi[fm][2], ahi[fm][3], ra);
                uint32_t rl = ra + (OFF_ALO - OFF_AHI);
                LDSM_X4(alo[fm][0], alo[fm][1], alo[fm][2], alo[fm][3], rl);
            }
#pragma unroll
            for (int fn = 0; fn < 4; fn++) {
                uint32_t rb = smb + OFF_BHI + (wn0 + fn*8 + b_row) * TSTRIDE + ks*32 + b_kb;
                LDSM_X2(bhi[fn][0], bhi[fn][1], rb);
                uint32_t rl = rb + (OFF_BLO - OFF_BHI);
                LDSM_X2(blo[fn][0], blo[fn][1], rl);
            }
#pragma unroll
            for (int fm = 0; fm < 4; fm++)
#pragma unroll
                for (int fn = 0; fn < 4; fn++) {
                    MMA16816(acc[fm][fn], ahi[fm][0],ahi[fm][1],ahi[fm][2],ahi[fm][3],
                             bhi[fn][0], bhi[fn][1]);
                    MMA16816(acc[fm][fn], ahi[fm][0],ahi[fm][1],ahi[fm][2],ahi[fm][3],
                             blo[fn][0], blo[fn][1]);
                    MMA16816(acc[fm][fn], alo[fm][0],alo[fm][1],alo[fm][2],alo[fm][3],
                             bhi[fn][0], bhi[fn][1]);
                }
        }
    }
    __syncthreads();

    // ---- epilogue ----
    int g  = lane >> 2;
    int tg = lane & 3;

    int   la8[8], lb8[8];
    float na8[8], nb8[8];
#pragma unroll
    for (int fm = 0; fm < 4; fm++)
#pragma unroll
        for (int h = 0; h < 2; h++) {
            int r = wm0 + fm*16 + g + h*8;
            la8[fm*2+h] = labA[r];
            if (PASS == 2) na8[fm*2+h] = negA[r];
        }
#pragma unroll
    for (int fn = 0; fn < 4; fn++)
#pragma unroll
        for (int p = 0; p < 2; p++) {
            int c = wn0 + fn*8 + tg*2 + p;
            lb8[fn*2+p] = labB[c];
            if (PASS == 2) nb8[fn*2+p] = negB[c];
        }

    float rowa[8] = {0,0,0,0,0,0,0,0};
    float cola[8] = {0,0,0,0,0,0,0,0};
    float rowc[8] = {0,0,0,0,0,0,0,0};
    float colc[8] = {0,0,0,0,0,0,0,0};

#pragma unroll
    for (int fm = 0; fm < 4; fm++)
#pragma unroll
        for (int fn = 0; fn < 4; fn++)
#pragma unroll
            for (int k = 0; k < 4; k++) {
                int h = k >> 1, p = k & 1;
                int ri = fm*2 + h, ci = fn*2 + p;
                float sv = acc[fm][fn][k];
                if (PASS == 1) {
                    if (la8[ri] != lb8[ci]) {
                        float e = __expf(sv * INV_T);
                        rowa[ri] += e;
                        cola[ci] += e;
                    }
                } else {
                    int grow = i0 + wm0 + fm*16 + g + h*8;
                    int gcol = j0 + wn0 + fn*8 + tg*2 + p;
                    if (la8[ri] == lb8[ci] && grow != gcol) {
                        float xm = __expf(-sv * INV_T);
                        rowa[ri] += __logf(fmaf(na8[ri], xm, 1.0f));
                        rowc[ri] += 1.0f;
                        cola[ci] += __logf(fmaf(nb8[ci], xm, 1.0f));
                        colc[ci] += 1.0f;
                    }
                }
            }

    // reduce rows across tg (xor 1,2), cols across g (xor 4,8,16)
#pragma unroll
    for (int r = 0; r < 8; r++) {
        rowa[r] += __shfl_xor_sync(0xffffffffu, rowa[r], 1);
        rowa[r] += __shfl_xor_sync(0xffffffffu, rowa[r], 2);
        cola[r] += __shfl_xor_sync(0xffffffffu, cola[r], 4);
        cola[r] += __shfl_xor_sync(0xffffffffu, cola[r], 8);
        cola[r] += __shfl_xor_sync(0xffffffffu, cola[r], 16);
        if (PASS == 2) {
            rowc[r] += __shfl_xor_sync(0xffffffffu, rowc[r], 1);
            rowc[r] += __shfl_xor_sync(0xffffffffu, rowc[r], 2);
            colc[r] += __shfl_xor_sync(0xffffffffu, colc[r], 4);
            colc[r] += __shfl_xor_sync(0xffffffffu, colc[r], 8);
            colc[r] += __shfl_xor_sync(0xffffffffu, colc[r], 16);
        }
    }

    if (tg == 0) {
#pragma unroll
        for (int ri = 0; ri < 8; ri++) {
            int r = wm0 + (ri >> 1)*16 + g + (ri & 1)*8;
            atomicAdd(&srow[r], rowa[ri]);
            if (PASS == 2) atomicAdd(&scnr[r], rowc[ri]);
        }
    }
    if (g == 0) {
#pragma unroll
        for (int ci = 0; ci < 8; ci++) {
            int c = wn0 + (ci >> 1)*8 + tg*2 + (ci & 1);
            atomicAdd(&scol[c], cola[ci]);
            if (PASS == 2) atomicAdd(&scnc[c], colc[ci]);
        }
    }
    __syncthreads();

    if (tid < 128) {
        if (PASS == 1) {
            atomicAdd(&g_neg[i0 + tid], srow[tid]);
            if (offdiag) atomicAdd(&g_neg[j0 + tid], scol[tid]);
        } else {
            atomicAdd(&g_row[i0 + tid], srow[tid]);
            atomicAdd(&g_cnt[i0 + tid], scnr[tid]);
            if (offdiag) {
                atomicAdd(&g_row[j0 + tid], scol[tid]);
                atomicAdd(&g_cnt[j0 + tid], scnc[tid]);
            }
        }
    }
}

// ---------------------------------------------------------------------------
__global__ void final_kernel(float* __restrict__ out, int N)
{
    __shared__ float sred[1024];
    __shared__ int   ired[1024];
    int tid = threadIdx.x;

    float sum = 0.0f; int vc = 0;
    for (int i = tid; i < N; i += 1024) {
        float c = g_cnt[i];
        if (c > 0.5f) { sum += g_row[i] / c; vc++; }
    }
    sred[tid] = sum; ired[tid] = vc;
    __syncthreads();
    for (int s = 512; s; s >>= 1) {
        if (tid < s) { sred[tid] += sred[tid + s]; ired[tid] += ired[tid + s]; }
        __syncthreads();
    }
    if (tid == 0) out[0] = (ired[0] > 0) ? sred[0] / (float)ired[0] : 0.0f;
}

// ---------------------------------------------------------------------------
extern "C" void kernel_launch(void* const* d_in, const int* in_sizes, int n_in,
                              void* d_out, int out_size)
{
    const float*        x   = (const float*)d_in[0];
    const unsigned int* lv  = (const unsigned int*)d_in[1];
    float*              out = (float*)d_out;

    int N = in_sizes[1];
    if (N > NMAX) N = NMAX;

    cudaFuncSetAttribute(pass_kernel<1>, cudaFuncAttributeMaxDynamicSharedMemorySize, SMEM_TOTAL);
    cudaFuncSetAttribute(pass_kernel<2>, cudaFuncAttributeMaxDynamicSharedMemorySize, SMEM_TOTAL);

    lab_kernel<<<1, 1024>>>(lv, N);
    prep_kernel<<<(N + 7) / 8, 256>>>(x, N);

    int T = N / 128;
    dim3 grid(T, T);
    pass_kernel<1><<<grid, 256, SMEM_TOTAL>>>(N);
    pass_kernel<2><<<grid, 256, SMEM_TOTAL>>>(N);

    final_kernel<<<1, 1024>>>(out, N);
}

// round 9
// speedup vs baseline: 2.4791x; 1.0365x over previous
#include <cuda_runtime.h>
#include <cuda_bf16.h>
#include <stdint.h>

// SupervisedContrastiveLoss on GB300 (sm_103) — mma.sync bf16 split GEMM,
// now with cp.async double-buffered mainloop (R6 was serial load->sync->MMA,
// tensor pipe only 33.7% busy).
//   h = x/||x||; h = hi + lo (bf16 split); s ≈ hi*hi^T + hi*lo^T + lo*hi^T (fp32 accum)
//   pass1: neg_sum[i] = sum_{lab_j != lab_i} exp(s_ij/T)
//   pass2: row_sum[i] = sum_{lab_j==lab_i, j!=i} log(1+neg_sum[i]*exp(-s_ij/T)); pos_cnt counted
//   out = mean over valid rows of row_sum/pos_cnt
// Symmetric: tiles bj >= bi only; off-diag tiles feed row and col accumulators.

#define NMAX 8192
#define D    256
#define INV_T 14.285714285714285714f

__device__ uint4 g_hi4[NMAX * D * 2 / 16];   // bf16 [NMAX][D]
__device__ uint4 g_lo4[NMAX * D * 2 / 16];
__device__ float g_neg[NMAX];
__device__ float g_row[NMAX];
__device__ float g_cnt[NMAX];
__device__ int   g_lab[NMAX];

// ---------------- PTX helpers (sm_80-era, valid on plain sm_103) ------------
__device__ __forceinline__ uint32_t smem_u32(const void* p) {
    uint32_t a;
    asm("{ .reg .u64 t; cvta.to.shared.u64 t, %1; cvt.u32.u64 %0, t; }" : "=r"(a) : "l"(p));
    return a;
}

#define CP_ASYNC16(dst, src) \
    asm volatile("cp.async.cg.shared.global [%0], [%1], 16;" :: "r"(dst), "l"(src) : "memory")
#define CP_COMMIT() asm volatile("cp.async.commit_group;" ::: "memory")
#define CP_WAIT0()  asm volatile("cp.async.wait_group 0;" ::: "memory")

#define LDSM_X4(r0,r1,r2,r3,addr) \
    asm volatile("ldmatrix.sync.aligned.m8n8.x4.shared.b16 {%0,%1,%2,%3}, [%4];" \
        : "=r"(r0),"=r"(r1),"=r"(r2),"=r"(r3) : "r"(addr))
#define LDSM_X2(r0,r1,addr) \
    asm volatile("ldmatrix.sync.aligned.m8n8.x2.shared.b16 {%0,%1}, [%2];" \
        : "=r"(r0),"=r"(r1) : "r"(addr))
#define MMA16816(d,a0,a1,a2,a3,b0,b1) \
    asm volatile("mma.sync.aligned.m16n8k16.row.col.f32.bf16.bf16.f32 " \
        "{%0,%1,%2,%3}, {%4,%5,%6,%7}, {%8,%9}, {%0,%1,%2,%3};" \
        : "+f"((d)[0]),"+f"((d)[1]),"+f"((d)[2]),"+f"((d)[3]) \
        : "r"(a0),"r"(a1),"r"(a2),"r"(a3),"r"(b0),"r"(b1))

// -------------------- dynamic SMEM layout (bytes) ---------------------------
#define SM_LABA   0        // int[128]
#define SM_LABB   512
#define SM_NEGA   1024     // float[128]
#define SM_NEGB   1536
#define SM_SROW   2048     // float[128]
#define SM_SCOL   2560
#define SM_SCNR   3072
#define SM_SCNC   3584
#define SM_TILE   4096
#define TSTRIDE   144      // 128B data + 16B pad -> ldmatrix phase covers all 32 banks
#define TBYTES    (128 * TSTRIDE)        // 18432
#define STAGE     (4 * TBYTES)           // 73728 per stage (Ahi|Alo|Bhi|Blo)
#define SMEM_TOTAL (SM_TILE + 2 * STAGE) // 151552

// ---------------------------------------------------------------------------
// Label ingest, robust to int32 vs int64 storage (equality-only semantics).
// ---------------------------------------------------------------------------
__global__ void lab_kernel(const unsigned int* __restrict__ v, int N)
{
    __shared__ int s_or[1024];
    int tid = threadIdx.x;
    unsigned int o = 0;
    for (int i = 2 * tid + 1; i < N; i += 2048) o |= v[i];
    s_or[tid] = (o != 0);
    __syncthreads();
    for (int s = 512; s; s >>= 1) { if (tid < s) s_or[tid] |= s_or[tid + s]; __syncthreads(); }
    int is32 = s_or[0];
    for (int i = tid; i < N; i += 1024)
        g_lab[i] = is32 ? (int)v[i] : (int)v[2 * i];
}

// ---------------------------------------------------------------------------
// Normalize + bf16 hi/lo split. 256 threads = 8 warps, one warp per row.
// ---------------------------------------------------------------------------
__global__ __launch_bounds__(256) void prep_kernel(const float* __restrict__ x, int N)
{
    int row  = blockIdx.x * 8 + (threadIdx.x >> 5);
    if (row >= N) return;
    int lane = threadIdx.x & 31;

    const float4* x4 = reinterpret_cast<const float4*>(x + (size_t)row * D);
    float4 a = x4[lane];
    float4 b = x4[lane + 32];

    float ss = a.x*a.x + a.y*a.y + a.z*a.z + a.w*a.w
             + b.x*b.x + b.y*b.y + b.z*b.z + b.w*b.w;
#pragma unroll
    for (int o = 16; o; o >>= 1) ss += __shfl_xor_sync(0xffffffffu, ss, o);

    float inv = 1.0f / fmaxf(sqrtf(ss), 1e-12f);
    a.x *= inv; a.y *= inv; a.z *= inv; a.w *= inv;
    b.x *= inv; b.y *= inv; b.z *= inv; b.w *= inv;

    __nv_bfloat162* hi2 = reinterpret_cast<__nv_bfloat162*>(g_hi4);
    __nv_bfloat162* lo2 = reinterpret_cast<__nv_bfloat162*>(g_lo4);
    size_t base = (size_t)row * (D / 2);

    float vals[8] = {a.x, a.y, a.z, a.w, b.x, b.y, b.z, b.w};
#pragma unroll
    for (int p = 0; p < 4; p++) {
        float u = vals[2*p], v = vals[2*p+1];
        __nv_bfloat16 hu = __float2bfloat16(u);
        __nv_bfloat16 hv = __float2bfloat16(v);
        __nv_bfloat162 H; H.x = hu; H.y = hv;
        __nv_bfloat162 L; L.x = __float2bfloat16(u - __bfloat162float(hu));
        L.y = __float2bfloat16(v - __bfloat162float(hv));
        size_t idx2 = base + ((p < 2) ? (lane*2 + p) : (64 + lane*2 + (p-2)));
        hi2[idx2] = H;
        lo2[idx2] = L;
    }

    if (lane == 0) { g_neg[row] = 0.0f; g_row[row] = 0.0f; g_cnt[row] = 0.0f; }
}

// Issue the 16 cp.async ops that fill one stage with chunk kc's four tiles.
__device__ __forceinline__ void issue_stage(uint32_t smb, int stage, int kc,
                                            int i0, int j0, int tid,
                                            const char* hi_base, const char* lo_base)
{
    uint32_t sbase = smb + SM_TILE + stage * STAGE;
#pragma unroll
    for (int t = 0; t < 16; t++) {
        int idx = tid + t * 256;
        int mat = idx >> 10;          // 0 Ahi, 1 Alo, 2 Bhi, 3 Blo
        int rem = idx & 1023;
        int row = rem >> 3;
        int c   = rem & 7;
        int grow = (mat < 2) ? (i0 + row) : (j0 + row);
        const char* src = ((mat & 1) ? lo_base : hi_base)
                        + (size_t)grow * 512 + kc * 128 + c * 16;
        uint32_t dst = sbase + mat * TBYTES + row * TSTRIDE + c * 16;
        CP_ASYNC16(dst, src);
    }
    CP_COMMIT();
}

// ---------------------------------------------------------------------------
// Pass kernel: 128x128 tile via mma.sync bf16, symmetric upper-triangle grid,
// cp.async 2-stage pipeline over K chunks of 64.
// 8 warps: warp tile 64x32 (wm = wid&1 -> 64 rows, wn = wid>>1 -> 32 cols).
// ---------------------------------------------------------------------------
template <int PASS>
__global__ __launch_bounds__(256, 1) void pass_kernel(int N)
{
    extern __shared__ char sm[];
    int bi = blockIdx.y, bj = blockIdx.x;
    if (bj < bi) return;

    int tid  = threadIdx.x;
    int wid  = tid >> 5;
    int lane = tid & 31;
    int i0 = bi * 128, j0 = bj * 128;
    bool offdiag = (bi != bj);
    uint32_t smb = smem_u32(sm);

    int* labA   = (int*)(sm + SM_LABA);
    int* labB   = (int*)(sm + SM_LABB);
    float* negA = (float*)(sm + SM_NEGA);
    float* negB = (float*)(sm + SM_NEGB);
    float* srow = (float*)(sm + SM_SROW);
    float* scol = (float*)(sm + SM_SCOL);
    float* scnr = (float*)(sm + SM_SCNR);
    float* scnc = (float*)(sm + SM_SCNC);

    const char* hi_base = (const char*)g_hi4;
    const char* lo_base = (const char*)g_lo4;

    // kick off stage 0 (chunk 0) before anything else
    issue_stage(smb, 0, 0, i0, j0, tid, hi_base, lo_base);

    if (tid < 128) {
        labA[tid] = g_lab[i0 + tid];
        labB[tid] = g_lab[j0 + tid];
        srow[tid] = 0.0f; scol[tid] = 0.0f;
        if (PASS == 2) {
            negA[tid] = g_neg[i0 + tid];
            negB[tid] = g_neg[j0 + tid];
            scnr[tid] = 0.0f; scnc[tid] = 0.0f;
        }
    }

    int wm0 = (wid & 1) * 64;
    int wn0 = (wid >> 1) * 32;

    float acc[4][4][4];
#pragma unroll
    for (int fm = 0; fm < 4; fm++)
#pragma unroll
        for (int fn = 0; fn < 4; fn++)
#pragma unroll
            for (int k = 0; k < 4; k++) acc[fm][fn][k] = 0.0f;

    // fragment smem address components (per-lane constant)
    int a_row = lane & 15;                 // + fm*16 (+wm0)
    int a_kb  = (lane >> 4) * 16;          // + ks*32
    int b_row = lane & 7;                  // + fn*8 (+wn0)
    int b_kb  = ((lane >> 3) & 1) * 16;    // + ks*32

#pragma unroll
    for (int kc = 0; kc < 4; kc++) {       // K chunks of 64
        int s = kc & 1;
        CP_WAIT0();                        // stage s data landed
        __syncthreads();                   // ..and all warps done with stage s's prior use
        if (kc < 3)
            issue_stage(smb, s ^ 1, kc + 1, i0, j0, tid, hi_base, lo_base);

        uint32_t off_ahi = SM_TILE + s * STAGE;
#pragma unroll
        for (int ks = 0; ks < 4; ks++) {   // k16 steps within chunk
            uint32_t ahi[4][4], alo[4][4], bhi[4][2], blo[4][2];
#pragma unroll
            for (int fm = 0; fm < 4; fm++) {
                uint32_t ra = smb + off_ahi + (wm0 + fm*16 + a_row) * TSTRIDE + ks*32 + a_kb;
                LDSM_X4(ahi[fm][0], ahi[fm][1], ahi[fm][2], ahi[fm][3], ra);
                LDSM_X4(alo[fm][0], alo[fm][1], alo[fm][2], alo[fm][3], ra + TBYTES);
            }
#pragma unroll
            for (int fn = 0; fn < 4; fn++) {
                uint32_t rb = smb + off_ahi + 2*TBYTES + (wn0 + fn*8 + b_row) * TSTRIDE + ks*32 + b_kb;
                LDSM_X2(bhi[fn][0], bhi[fn][1], rb);
                LDSM_X2(blo[fn][0], blo[fn][1], rb + TBYTES);
            }
#pragma unroll
            for (int fm = 0; fm < 4; fm++)
#pragma unroll
                for (int fn = 0; fn < 4; fn++) {
                    MMA16816(acc[fm][fn], ahi[fm][0],ahi[fm][1],ahi[fm][2],ahi[fm][3],
                             bhi[fn][0], bhi[fn][1]);
                    MMA16816(acc[fm][fn], ahi[fm][0],ahi[fm][1],ahi[fm][2],ahi[fm][3],
                             blo[fn][0], blo[fn][1]);
                    MMA16816(acc[fm][fn], alo[fm][0],alo[fm][1],alo[fm][2],alo[fm][3],
                             bhi[fn][0], bhi[fn][1]);
                }
        }
        __syncthreads();                   // stage s consumed; safe to overwrite next round
    }

    // ---- epilogue ----
    int g  = lane >> 2;
    int tg = lane & 3;

    int   la8[8], lb8[8];
    float na8[8], nb8[8];
#pragma unroll
    for (int fm = 0; fm < 4; fm++)
#pragma unroll
        for (int h = 0; h < 2; h++) {
            int r = wm0 + fm*16 + g + h*8;
            la8[fm*2+h] = labA[r];
            if (PASS == 2) na8[fm*2+h] = negA[r];
        }
#pragma unroll
    for (int fn = 0; fn < 4; fn++)
#pragma unroll
        for (int p = 0; p < 2; p++) {
            int c = wn0 + fn*8 + tg*2 + p;
            lb8[fn*2+p] = labB[c];
            if (PASS == 2) nb8[fn*2+p] = negB[c];
        }

    float rowa[8] = {0,0,0,0,0,0,0,0};
    float cola[8] = {0,0,0,0,0,0,0,0};
    float rowc[8] = {0,0,0,0,0,0,0,0};
    float colc[8] = {0,0,0,0,0,0,0,0};

#pragma unroll
    for (int fm = 0; fm < 4; fm++)
#pragma unroll
        for (int fn = 0; fn < 4; fn++)
#pragma unroll
            for (int k = 0; k < 4; k++) {
                int h = k >> 1, p = k & 1;
                int ri = fm*2 + h, ci = fn*2 + p;
                float sv = acc[fm][fn][k];
                if (PASS == 1) {
                    if (la8[ri] != lb8[ci]) {
                        float e = __expf(sv * INV_T);
                        rowa[ri] += e;
                        cola[ci] += e;
                    }
                } else {
                    int grow = i0 + wm0 + fm*16 + g + h*8;
                    int gcol = j0 + wn0 + fn*8 + tg*2 + p;
                    if (la8[ri] == lb8[ci] && grow != gcol) {
                        float xm = __expf(-sv * INV_T);
                        rowa[ri] += __logf(fmaf(na8[ri], xm, 1.0f));
                        rowc[ri] += 1.0f;
                        cola[ci] += __logf(fmaf(nb8[ci], xm, 1.0f));
                        colc[ci] += 1.0f;
                    }
                }
            }

    // reduce rows across tg (xor 1,2), cols across g (xor 4,8,16)
#pragma unroll
    for (int r = 0; r < 8; r++) {
        rowa[r] += __shfl_xor_sync(0xffffffffu, rowa[r], 1);
        rowa[r] += __shfl_xor_sync(0xffffffffu, rowa[r], 2);
        cola[r] += __shfl_xor_sync(0xffffffffu, cola[r], 4);
        cola[r] += __shfl_xor_sync(0xffffffffu, cola[r], 8);
        cola[r] += __shfl_xor_sync(0xffffffffu, cola[r], 16);
        if (PASS == 2) {
            rowc[r] += __shfl_xor_sync(0xffffffffu, rowc[r], 1);
            rowc[r] += __shfl_xor_sync(0xffffffffu, rowc[r], 2);
            colc[r] += __shfl_xor_sync(0xffffffffu, colc[r], 4);
            colc[r] += __shfl_xor_sync(0xffffffffu, colc[r], 8);
            colc[r] += __shfl_xor_sync(0xffffffffu, colc[r], 16);
        }
    }

    if (tg == 0) {
#pragma unroll
        for (int ri = 0; ri < 8; ri++) {
            int r = wm0 + (ri >> 1)*16 + g + (ri & 1)*8;
            atomicAdd(&srow[r], rowa[ri]);
            if (PASS == 2) atomicAdd(&scnr[r], rowc[ri]);
        }
    }
    if (g == 0) {
#pragma unroll
        for (int ci = 0; ci < 8; ci++) {
            int c = wn0 + (ci >> 1)*8 + tg*2 + (ci & 1);
            atomicAdd(&scol[c], cola[ci]);
            if (PASS == 2) atomicAdd(&scnc[c], colc[ci]);
        }
    }
    __syncthreads();

    if (tid < 128) {
        if (PASS == 1) {
            atomicAdd(&g_neg[i0 + tid], srow[tid]);
            if (offdiag) atomicAdd(&g_neg[j0 + tid], scol[tid]);
        } else {
            atomicAdd(&g_row[i0 + tid], srow[tid]);
            atomicAdd(&g_cnt[i0 + tid], scnr[tid]);
            if (offdiag) {
                atomicAdd(&g_row[j0 + tid], scol[tid]);
                atomicAdd(&g_cnt[j0 + tid], scnc[tid]);
            }
        }
    }
}

// ---------------------------------------------------------------------------
__global__ void final_kernel(float* __restrict__ out, int N)
{
    __shared__ float sred[1024];
    __shared__ int   ired[1024];
    int tid = threadIdx.x;

    float sum = 0.0f; int vc = 0;
    for (int i = tid; i < N; i += 1024) {
        float c = g_cnt[i];
        if (c > 0.5f) { sum += g_row[i] / c; vc++; }
    }
    sred[tid] = sum; ired[tid] = vc;
    __syncthreads();
    for (int s = 512; s; s >>= 1) {
        if (tid < s) { sred[tid] += sred[tid + s]; ired[tid] += ired[tid + s]; }
        __syncthreads();
    }
    if (tid == 0) out[0] = (ired[0] > 0) ? sred[0] / (float)ired[0] : 0.0f;
}

// ---------------------------------------------------------------------------
extern "C" void kernel_launch(void* const* d_in, const int* in_sizes, int n_in,
                              void* d_out, int out_size)
{
    const float*        x   = (const float*)d_in[0];
    const unsigned int* lv  = (const unsigned int*)d_in[1];
    float*              out = (float*)d_out;

    int N = in_sizes[1];
    if (N > NMAX) N = NMAX;

    cudaFuncSetAttribute(pass_kernel<1>, cudaFuncAttributeMaxDynamicSharedMemorySize, SMEM_TOTAL);
    cudaFuncSetAttribute(pass_kernel<2>, cudaFuncAttributeMaxDynamicSharedMemorySize, SMEM_TOTAL);

    lab_kernel<<<1, 1024>>>(lv, N);
    prep_kernel<<<(N + 7) / 8, 256>>>(x, N);

    int T = N / 128;
    dim3 grid(T, T);
    pass_kernel<1><<<grid, 256, SMEM_TOTAL>>>(N);
    pass_kernel<2><<<grid, 256, SMEM_TOTAL>>>(N);

    final_kernel<<<1, 1024>>>(out, N);
}

// round 11
// speedup vs baseline: 3.3940x; 1.3691x over previous
#include <cuda_runtime.h>
#include <cuda_bf16.h>
#include <stdint.h>

// SupervisedContrastiveLoss on GB300 (sm_103) — mma.sync bf16 split GEMM.
// R9 lesson: pass kernels are latency-bound at 1 CTA/SM, not load-bound.
// This round: compute sim ONCE (pass1), cache tiles to a device scratch in
// thread-linear layout; pass2 becomes a GEMM-free, high-occupancy epilogue.
//   h = x/||x||; h = hi + lo (bf16 split); s ≈ hi*hi^T + hi*lo^T + lo*hi^T
//   pass1: neg_sum[i] = sum_{lab_j != lab_i} exp(s_ij/T); stores s tiles
//   pass2: row_sum[i] = sum_{lab_j==lab_i, j!=i} log(1+neg_sum[i]*exp(-s_ij/T))
//   out = mean over valid rows of row_sum/pos_cnt
// Symmetric: tiles bj >= bi only; off-diag tiles feed row and col accumulators.

#define NMAX 8192
#define D    256
#define INV_T 14.285714285714285714f
#define TMAXT (NMAX / 128)                     // 64 tile-rows
#define NTILES (TMAXT * (TMAXT + 1) / 2)       // 2080 upper-tri tiles

__device__ uint4  g_hi4[NMAX * D * 2 / 16];    // bf16 [NMAX][D]
__device__ uint4  g_lo4[NMAX * D * 2 / 16];
__device__ float4 g_sim4[(size_t)NTILES * 4096];  // 136MB sim cache, thread-linear
__device__ float  g_neg[NMAX];
__device__ float  g_row[NMAX];
__device__ float  g_cnt[NMAX];
__device__ int    g_lab[NMAX];

// ---------------- PTX helpers (sm_80-era, valid on plain sm_103) ------------
__device__ __forceinline__ uint32_t smem_u32(const void* p) {
    uint32_t a;
    asm("{ .reg .u64 t; cvta.to.shared.u64 t, %1; cvt.u32.u64 %0, t; }" : "=r"(a) : "l"(p));
    return a;
}

#define CP_ASYNC16(dst, src) \
    asm volatile("cp.async.cg.shared.global [%0], [%1], 16;" :: "r"(dst), "l"(src) : "memory")
#define CP_COMMIT() asm volatile("cp.async.commit_group;" ::: "memory")
#define CP_WAIT0()  asm volatile("cp.async.wait_group 0;" ::: "memory")

#define LDSM_X4(r0,r1,r2,r3,addr) \
    asm volatile("ldmatrix.sync.aligned.m8n8.x4.shared.b16 {%0,%1,%2,%3}, [%4];" \
        : "=r"(r0),"=r"(r1),"=r"(r2),"=r"(r3) : "r"(addr))
#define LDSM_X2(r0,r1,addr) \
    asm volatile("ldmatrix.sync.aligned.m8n8.x2.shared.b16 {%0,%1}, [%2];" \
        : "=r"(r0),"=r"(r1) : "r"(addr))
#define MMA16816(d,a0,a1,a2,a3,b0,b1) \
    asm volatile("mma.sync.aligned.m16n8k16.row.col.f32.bf16.bf16.f32 " \
        "{%0,%1,%2,%3}, {%4,%5,%6,%7}, {%8,%9}, {%0,%1,%2,%3};" \
        : "+f"((d)[0]),"+f"((d)[1]),"+f"((d)[2]),"+f"((d)[3]) \
        : "r"(a0),"r"(a1),"r"(a2),"r"(a3),"r"(b0),"r"(b1))

// -------------------- dynamic SMEM layout for pass1 (bytes) -----------------
#define SM_LABA   0        // int[128]
#define SM_LABB   512
#define SM_SROW   1024     // float[128]
#define SM_SCOL   1536
#define SM_TILE   2048
#define TSTRIDE   144      // 128B data + 16B pad -> ldmatrix phase covers all 32 banks
#define TBYTES    (128 * TSTRIDE)        // 18432
#define STAGE     (4 * TBYTES)           // 73728 per stage (Ahi|Alo|Bhi|Blo)
#define SMEM_TOTAL (SM_TILE + 2 * STAGE) // 149504

// ---------------------------------------------------------------------------
// Label ingest, robust to int32 vs int64 storage (equality-only semantics).
// ---------------------------------------------------------------------------
__global__ void lab_kernel(const unsigned int* __restrict__ v, int N)
{
    __shared__ int s_or[1024];
    int tid = threadIdx.x;
    unsigned int o = 0;
    for (int i = 2 * tid + 1; i < N; i += 2048) o |= v[i];
    s_or[tid] = (o != 0);
    __syncthreads();
    for (int s = 512; s; s >>= 1) { if (tid < s) s_or[tid] |= s_or[tid + s]; __syncthreads(); }
    int is32 = s_or[0];
    for (int i = tid; i < N; i += 1024)
        g_lab[i] = is32 ? (int)v[i] : (int)v[2 * i];
}

// ---------------------------------------------------------------------------
// Normalize + bf16 hi/lo split. 256 threads = 8 warps, one warp per row.
// ---------------------------------------------------------------------------
__global__ __launch_bounds__(256) void prep_kernel(const float* __restrict__ x, int N)
{
    int row  = blockIdx.x * 8 + (threadIdx.x >> 5);
    if (row >= N) return;
    int lane = threadIdx.x & 31;

    const float4* x4 = reinterpret_cast<const float4*>(x + (size_t)row * D);
    float4 a = x4[lane];
    float4 b = x4[lane + 32];

    float ss = a.x*a.x + a.y*a.y + a.z*a.z + a.w*a.w
             + b.x*b.x + b.y*b.y + b.z*b.z + b.w*b.w;
#pragma unroll
    for (int o = 16; o; o >>= 1) ss += __shfl_xor_sync(0xffffffffu, ss, o);

    float inv = 1.0f / fmaxf(sqrtf(ss), 1e-12f);
    a.x *= inv; a.y *= inv; a.z *= inv; a.w *= inv;
    b.x *= inv; b.y *= inv; b.z *= inv; b.w *= inv;

    __nv_bfloat162* hi2 = reinterpret_cast<__nv_bfloat162*>(g_hi4);
    __nv_bfloat162* lo2 = reinterpret_cast<__nv_bfloat162*>(g_lo4);
    size_t base = (size_t)row * (D / 2);

    float vals[8] = {a.x, a.y, a.z, a.w, b.x, b.y, b.z, b.w};
#pragma unroll
    for (int p = 0; p < 4; p++) {
        float u = vals[2*p], v = vals[2*p+1];
        __nv_bfloat16 hu = __float2bfloat16(u);
        __nv_bfloat16 hv = __float2bfloat16(v);
        __nv_bfloat162 H; H.x = hu; H.y = hv;
        __nv_bfloat162 L; L.x = __float2bfloat16(u - __bfloat162float(hu));
        L.y = __float2bfloat16(v - __bfloat162float(hv));
        size_t idx2 = base + ((p < 2) ? (lane*2 + p) : (64 + lane*2 + (p-2)));
        hi2[idx2] = H;
        lo2[idx2] = L;
    }

    if (lane == 0) { g_neg[row] = 0.0f; g_row[row] = 0.0f; g_cnt[row] = 0.0f; }
}

// Issue the 16 cp.async ops that fill one stage with chunk kc's four tiles.
__device__ __forceinline__ void issue_stage(uint32_t smb, int stage, int kc,
                                            int i0, int j0, int tid,
                                            const char* hi_base, const char* lo_base)
{
    uint32_t sbase = smb + SM_TILE + stage * STAGE;
#pragma unroll
    for (int t = 0; t < 16; t++) {
        int idx = tid + t * 256;
        int mat = idx >> 10;          // 0 Ahi, 1 Alo, 2 Bhi, 3 Blo
        int rem = idx & 1023;
        int row = rem >> 3;
        int c   = rem & 7;
        int grow = (mat < 2) ? (i0 + row) : (j0 + row);
        const char* src = ((mat & 1) ? lo_base : hi_base)
                        + (size_t)grow * 512 + kc * 128 + c * 16;
        uint32_t dst = sbase + mat * TBYTES + row * TSTRIDE + c * 16;
        CP_ASYNC16(dst, src);
    }
    CP_COMMIT();
}

// ---------------------------------------------------------------------------
// Pass 1: GEMM (128x128 tile, mma.sync bf16 split), exp-mask neg sums,
// and store the raw sim tile to g_sim4 in thread-linear layout.
// ---------------------------------------------------------------------------
__global__ __launch_bounds__(256, 1) void pass1_kernel(int N)
{
    extern __shared__ char sm[];
    int bi = blockIdx.y, bj = blockIdx.x;
    if (bj < bi) return;

    int tid  = threadIdx.x;
    int wid  = tid >> 5;
    int lane = tid & 31;
    int i0 = bi * 128, j0 = bj * 128;
    bool offdiag = (bi != bj);
    uint32_t smb = smem_u32(sm);

    int* labA   = (int*)(sm + SM_LABA);
    int* labB   = (int*)(sm + SM_LABB);
    float* srow = (float*)(sm + SM_SROW);
    float* scol = (float*)(sm + SM_SCOL);

    const char* hi_base = (const char*)g_hi4;
    const char* lo_base = (const char*)g_lo4;

    issue_stage(smb, 0, 0, i0, j0, tid, hi_base, lo_base);

    if (tid < 128) {
        labA[tid] = g_lab[i0 + tid];
        labB[tid] = g_lab[j0 + tid];
        srow[tid] = 0.0f; scol[tid] = 0.0f;
    }

    int wm0 = (wid & 1) * 64;
    int wn0 = (wid >> 1) * 32;

    float acc[4][4][4];
#pragma unroll
    for (int fm = 0; fm < 4; fm++)
#pragma unroll
        for (int fn = 0; fn < 4; fn++)
#pragma unroll
            for (int k = 0; k < 4; k++) acc[fm][fn][k] = 0.0f;

    int a_row = lane & 15;
    int a_kb  = (lane >> 4) * 16;
    int b_row = lane & 7;
    int b_kb  = ((lane >> 3) & 1) * 16;

#pragma unroll
    for (int kc = 0; kc < 4; kc++) {
        int s = kc & 1;
        CP_WAIT0();
        __syncthreads();
        if (kc < 3)
            issue_stage(smb, s ^ 1, kc + 1, i0, j0, tid, hi_base, lo_base);

        uint32_t off_ahi = SM_TILE + s * STAGE;
#pragma unroll
        for (int ks = 0; ks < 4; ks++) {
            uint32_t ahi[4][4], alo[4][4], bhi[4][2], blo[4][2];
#pragma unroll
            for (int fm = 0; fm < 4; fm++) {
                uint32_t ra = smb + off_ahi + (wm0 + fm*16 + a_row) * TSTRIDE + ks*32 + a_kb;
                LDSM_X4(ahi[fm][0], ahi[fm][1], ahi[fm][2], ahi[fm][3], ra);
                LDSM_X4(alo[fm][0], alo[fm][1], alo[fm][2], alo[fm][3], ra + TBYTES);
            }
#pragma unroll
            for (int fn = 0; fn < 4; fn++) {
                uint32_t rb = smb + off_ahi + 2*TBYTES + (wn0 + fn*8 + b_row) * TSTRIDE + ks*32 + b_kb;
                LDSM_X2(bhi[fn][0], bhi[fn][1], rb);
                LDSM_X2(blo[fn][0], blo[fn][1], rb + TBYTES);
            }
#pragma unroll
            for (int fm = 0; fm < 4; fm++)
#pragma unroll
                for (int fn = 0; fn < 4; fn++) {
                    MMA16816(acc[fm][fn], ahi[fm][0],ahi[fm][1],ahi[fm][2],ahi[fm][3],
                             bhi[fn][0], bhi[fn][1]);
                    MMA16816(acc[fm][fn], ahi[fm][0],ahi[fm][1],ahi[fm][2],ahi[fm][3],
                             blo[fn][0], blo[fn][1]);
                    MMA16816(acc[fm][fn], alo[fm][0],alo[fm][1],alo[fm][2],alo[fm][3],
                             bhi[fn][0], bhi[fn][1]);
                }
        }
        __syncthreads();
    }

    // store raw sim tile (thread-linear: [tid][fm*4+fn] float4) — coalesced STG.128
    {
        int T = N >> 7;
        int tidx = bi * (2*T - bi + 1) / 2 + (bj - bi);
        float4* dst = g_sim4 + ((size_t)tidx << 12) + tid * 16;
#pragma unroll
        for (int fm = 0; fm < 4; fm++)
#pragma unroll
            for (int fn = 0; fn < 4; fn++)
                dst[fm*4 + fn] = make_float4(acc[fm][fn][0], acc[fm][fn][1],
                                             acc[fm][fn][2], acc[fm][fn][3]);
    }

    // ---- epilogue: masked exp, row + col negative sums ----
    int g  = lane >> 2;
    int tg = lane & 3;

    int la8[8], lb8[8];
#pragma unroll
    for (int fm = 0; fm < 4; fm++)
#pragma unroll
        for (int h = 0; h < 2; h++)
            la8[fm*2+h] = labA[wm0 + fm*16 + g + h*8];
#pragma unroll
    for (int fn = 0; fn < 4; fn++)
#pragma unroll
        for (int p = 0; p < 2; p++)
            lb8[fn*2+p] = labB[wn0 + fn*8 + tg*2 + p];

    float rowa[8] = {0,0,0,0,0,0,0,0};
    float cola[8] = {0,0,0,0,0,0,0,0};

#pragma unroll
    for (int fm = 0; fm < 4; fm++)
#pragma unroll
        for (int fn = 0; fn < 4; fn++)
#pragma unroll
            for (int k = 0; k < 4; k++) {
                int h = k >> 1, p = k & 1;
                int ri = fm*2 + h, ci = fn*2 + p;
                if (la8[ri] != lb8[ci]) {
                    float e = __expf(acc[fm][fn][k] * INV_T);
                    rowa[ri] += e;
                    cola[ci] += e;
                }
            }

#pragma unroll
    for (int r = 0; r < 8; r++) {
        rowa[r] += __shfl_xor_sync(0xffffffffu, rowa[r], 1);
        rowa[r] += __shfl_xor_sync(0xffffffffu, rowa[r], 2);
        cola[r] += __shfl_xor_sync(0xffffffffu, cola[r], 4);
        cola[r] += __shfl_xor_sync(0xffffffffu, cola[r], 8);
        cola[r] += __shfl_xor_sync(0xffffffffu, cola[r], 16);
    }

    if (tg == 0) {
#pragma unroll
        for (int ri = 0; ri < 8; ri++) {
            int r = wm0 + (ri >> 1)*16 + g + (ri & 1)*8;
            atomicAdd(&srow[r], rowa[ri]);
        }
    }
    if (g == 0) {
#pragma unroll
        for (int ci = 0; ci < 8; ci++) {
            int c = wn0 + (ci >> 1)*8 + tg*2 + (ci & 1);
            atomicAdd(&scol[c], cola[ci]);
        }
    }
    __syncthreads();

    if (tid < 128) {
        atomicAdd(&g_neg[i0 + tid], srow[tid]);
        if (offdiag) atomicAdd(&g_neg[j0 + tid], scol[tid]);
    }
}

// ---------------------------------------------------------------------------
// Pass 2 (lite): no GEMM. Reads the cached sim tile (coalesced float4),
// computes log(1 + neg*exp(-s/T)) for positive pairs, row + col accumulation.
// Tiny smem + modest regs -> high occupancy, latency-immune.
// ---------------------------------------------------------------------------
__global__ __launch_bounds__(256) void pass2_kernel(int N)
{
    __shared__ int   labA[128], labB[128];
    __shared__ float negA[128], negB[128];
    __shared__ float srow[128], scol[128], scnr[128], scnc[128];

    int bi = blockIdx.y, bj = blockIdx.x;
    if (bj < bi) return;

    int tid  = threadIdx.x;
    int wid  = tid >> 5;
    int lane = tid & 31;
    int i0 = bi * 128, j0 = bj * 128;
    bool offdiag = (bi != bj);

    if (tid < 128) {
        labA[tid] = g_lab[i0 + tid];
        labB[tid] = g_lab[j0 + tid];
        negA[tid] = g_neg[i0 + tid];
        negB[tid] = g_neg[j0 + tid];
        srow[tid] = 0.0f; scol[tid] = 0.0f;
        scnr[tid] = 0.0f; scnc[tid] = 0.0f;
    }
    __syncthreads();

    int wm0 = (wid & 1) * 64;
    int wn0 = (wid >> 1) * 32;
    int g   = lane >> 2;
    int tg  = lane & 3;

    int T = N >> 7;
    int tidx = bi * (2*T - bi + 1) / 2 + (bj - bi);
    const float4* src = g_sim4 + ((size_t)tidx << 12) + tid * 16;

    int   la8[8], lb8[8];
    float na8[8], nb8[8];
#pragma unroll
    for (int fm = 0; fm < 4; fm++)
#pragma unroll
        for (int h = 0; h < 2; h++) {
            int r = wm0 + fm*16 + g + h*8;
            la8[fm*2+h] = labA[r];
            na8[fm*2+h] = negA[r];
        }
#pragma unroll
    for (int fn = 0; fn < 4; fn++)
#pragma unroll
        for (int p = 0; p < 2; p++) {
            int c = wn0 + fn*8 + tg*2 + p;
            lb8[fn*2+p] = labB[c];
            nb8[fn*2+p] = negB[c];
        }

    float rowa[8] = {0,0,0,0,0,0,0,0};
    float cola[8] = {0,0,0,0,0,0,0,0};
    float rowc[8] = {0,0,0,0,0,0,0,0};
    float colc[8] = {0,0,0,0,0,0,0,0};

#pragma unroll
    for (int fm = 0; fm < 4; fm++)
#pragma unroll
        for (int fn = 0; fn < 4; fn++) {
            float4 v = src[fm*4 + fn];
            float sv4[4] = {v.x, v.y, v.z, v.w};
#pragma unroll
            for (int k = 0; k < 4; k++) {
                int h = k >> 1, p = k & 1;
                int ri = fm*2 + h, ci = fn*2 + p;
                int grow = i0 + wm0 + fm*16 + g + h*8;
                int gcol = j0 + wn0 + fn*8 + tg*2 + p;
                if (la8[ri] == lb8[ci] && grow != gcol) {
                    float xm = __expf(-sv4[k] * INV_T);
                    rowa[ri] += __logf(fmaf(na8[ri], xm, 1.0f));
                    rowc[ri] += 1.0f;
                    cola[ci] += __logf(fmaf(nb8[ci], xm, 1.0f));
                    colc[ci] += 1.0f;
                }
            }
        }

#pragma unroll
    for (int r = 0; r < 8; r++) {
        rowa[r] += __shfl_xor_sync(0xffffffffu, rowa[r], 1);
        rowa[r] += __shfl_xor_sync(0xffffffffu, rowa[r], 2);
        rowc[r] += __shfl_xor_sync(0xffffffffu, rowc[r], 1);
        rowc[r] += __shfl_xor_sync(0xffffffffu, rowc[r], 2);
        cola[r] += __shfl_xor_sync(0xffffffffu, cola[r], 4);
        cola[r] += __shfl_xor_sync(0xffffffffu, cola[r], 8);
        cola[r] += __shfl_xor_sync(0xffffffffu, cola[r], 16);
        colc[r] += __shfl_xor_sync(0xffffffffu, colc[r], 4);
        colc[r] += __shfl_xor_sync(0xffffffffu, colc[r], 8);
        colc[r] += __shfl_xor_sync(0xffffffffu, colc[r], 16);
    }

    if (tg == 0) {
#pragma unroll
        for (int ri = 0; ri < 8; ri++) {
            int r = wm0 + (ri >> 1)*16 + g + (ri & 1)*8;
            atomicAdd(&srow[r], rowa[ri]);
            atomicAdd(&scnr[r], rowc[ri]);
        }
    }
    if (g == 0) {
#pragma unroll
        for (int ci = 0; ci < 8; ci++) {
            int c = wn0 + (ci >> 1)*8 + tg*2 + (ci & 1);
            atomicAdd(&scol[c], cola[ci]);
            atomicAdd(&scnc[c], colc[ci]);
        }
    }
    __syncthreads();

    if (tid < 128) {
        atomicAdd(&g_row[i0 + tid], srow[tid]);
        atomicAdd(&g_cnt[i0 + tid], scnr[tid]);
        if (offdiag) {
            atomicAdd(&g_row[j0 + tid], scol[tid]);
            atomicAdd(&g_cnt[j0 + tid], scnc[tid]);
        }
    }
}

// ---------------------------------------------------------------------------
__global__ void final_kernel(float* __restrict__ out, int N)
{
    __shared__ float sred[1024];
    __shared__ int   ired[1024];
    int tid = threadIdx.x;

    float sum = 0.0f; int vc = 0;
    for (int i = tid; i < N; i += 1024) {
        float c = g_cnt[i];
        if (c > 0.5f) { sum += g_row[i] / c; vc++; }
    }
    sred[tid] = sum; ired[tid] = vc;
    __syncthreads();
    for (int s = 512; s; s >>= 1) {
        if (tid < s) { sred[tid] += sred[tid + s]; ired[tid] += ired[tid + s]; }
        __syncthreads();
    }
    if (tid == 0) out[0] = (ired[0] > 0) ? sred[0] / (float)ired[0] : 0.0f;
}

// ---------------------------------------------------------------------------
extern "C" void kernel_launch(void* const* d_in, const int* in_sizes, int n_in,
                              void* d_out, int out_size)
{
    const float*        x   = (const float*)d_in[0];
    const unsigned int* lv  = (const unsigned int*)d_in[1];
    float*              out = (float*)d_out;

    int N = in_sizes[1];
    if (N > NMAX) N = NMAX;

    cudaFuncSetAttribute(pass1_kernel, cudaFuncAttributeMaxDynamicSharedMemorySize, SMEM_TOTAL);

    lab_kernel<<<1, 1024>>>(lv, N);
    prep_kernel<<<(N + 7) / 8, 256>>>(x, N);

    int T = N / 128;
    dim3 grid(T, T);
    pass1_kernel<<<grid, 256, SMEM_TOTAL>>>(N);
    pass2_kernel<<<grid, 256>>>(N);

    final_kernel<<<1, 1024>>>(out, N);
}

// round 13
// speedup vs baseline: 5.5724x; 1.6418x over previous
#include <cuda_runtime.h>
#include <cuda_fp16.h>
#include <stdint.h>

// SupervisedContrastiveLoss on GB300 (sm_103) — single fp16 mma.sync GEMM.
// R11 lesson: pass1 (bf16 3-MMA split) was 63% of runtime at 35% tensor util.
// fp16's 11-bit mantissa makes ONE MMA per tile-k sufficient (predicted final
// rel_err ~1e-5 vs 1e-3 threshold): 3x less tensor work, half the loads,
// 37KB/stage smem -> 2 CTAs/SM for latency hiding.
//   h = x/||x||  (stored fp16)
//   pass1: s = h*h^T (fp32 accum); neg_sum[i] = sum_{lab_j != lab_i} exp(s/T);
//          sim tiles cached to scratch (thread-linear, coalesced)
//   pass2: row_sum[i] = sum_{lab_j==lab_i, j!=i} log(1+neg_sum[i]*exp(-s/T))
//   out = mean over valid rows of row_sum/pos_cnt
// Symmetric: tiles bj >= bi only; off-diag tiles feed row and col accumulators.

#define NMAX 8192
#define D    256
#define INV_T 14.285714285714285714f
#define TMAXT (NMAX / 128)                     // 64 tile-rows
#define NTILES (TMAXT * (TMAXT + 1) / 2)       // 2080 upper-tri tiles

__device__ uint4  g_h4[NMAX * D * 2 / 16];     // fp16 [NMAX][D]
__device__ float4 g_sim4[(size_t)NTILES * 4096];  // 136MB sim cache, thread-linear
__device__ float  g_neg[NMAX];
__device__ float  g_row[NMAX];
__device__ float  g_cnt[NMAX];
__device__ int    g_lab[NMAX];

// ---------------- PTX helpers (sm_80-era, valid on plain sm_103) ------------
__device__ __forceinline__ uint32_t smem_u32(const void* p) {
    uint32_t a;
    asm("{ .reg .u64 t; cvta.to.shared.u64 t, %1; cvt.u32.u64 %0, t; }" : "=r"(a) : "l"(p));
    return a;
}

#define CP_ASYNC16(dst, src) \
    asm volatile("cp.async.cg.shared.global [%0], [%1], 16;" :: "r"(dst), "l"(src) : "memory")
#define CP_COMMIT() asm volatile("cp.async.commit_group;" ::: "memory")
#define CP_WAIT0()  asm volatile("cp.async.wait_group 0;" ::: "memory")

#define LDSM_X4(r0,r1,r2,r3,addr) \
    asm volatile("ldmatrix.sync.aligned.m8n8.x4.shared.b16 {%0,%1,%2,%3}, [%4];" \
        : "=r"(r0),"=r"(r1),"=r"(r2),"=r"(r3) : "r"(addr))
#define LDSM_X2(r0,r1,addr) \
    asm volatile("ldmatrix.sync.aligned.m8n8.x2.shared.b16 {%0,%1}, [%2];" \
        : "=r"(r0),"=r"(r1) : "r"(addr))
#define MMAF16(d,a0,a1,a2,a3,b0,b1) \
    asm volatile("mma.sync.aligned.m16n8k16.row.col.f32.f16.f16.f32 " \
        "{%0,%1,%2,%3}, {%4,%5,%6,%7}, {%8,%9}, {%0,%1,%2,%3};" \
        : "+f"((d)[0]),"+f"((d)[1]),"+f"((d)[2]),"+f"((d)[3]) \
        : "r"(a0),"r"(a1),"r"(a2),"r"(a3),"r"(b0),"r"(b1))

// -------------------- dynamic SMEM layout for pass1 (bytes) -----------------
#define SM_LABA   0        // int[128]
#define SM_LABB   512
#define SM_SROW   1024     // float[128]
#define SM_SCOL   1536
#define SM_TILE   2048
#define TSTRIDE   144      // 128B data + 16B pad -> ldmatrix phase covers all 32 banks
#define TBYTES    (128 * TSTRIDE)        // 18432
#define STAGE     (2 * TBYTES)           // 36864 per stage (A|B)
#define SMEM_TOTAL (SM_TILE + 2 * STAGE) // 75776 -> 2 CTAs/SM

// ---------------------------------------------------------------------------
// Label ingest, robust to int32 vs int64 storage (equality-only semantics).
// ---------------------------------------------------------------------------
__global__ void lab_kernel(const unsigned int* __restrict__ v, int N)
{
    __shared__ int s_or[1024];
    int tid = threadIdx.x;
    unsigned int o = 0;
    for (int i = 2 * tid + 1; i < N; i += 2048) o |= v[i];
    s_or[tid] = (o != 0);
    __syncthreads();
    for (int s = 512; s; s >>= 1) { if (tid < s) s_or[tid] |= s_or[tid + s]; __syncthreads(); }
    int is32 = s_or[0];
    for (int i = tid; i < N; i += 1024)
        g_lab[i] = is32 ? (int)v[i] : (int)v[2 * i];
}

// ---------------------------------------------------------------------------
// Normalize + fp16 convert. 256 threads = 8 warps, one warp per row.
// ---------------------------------------------------------------------------
__global__ __launch_bounds__(256) void prep_kernel(const float* __restrict__ x, int N)
{
    int row  = blockIdx.x * 8 + (threadIdx.x >> 5);
    if (row >= N) return;
    int lane = threadIdx.x & 31;

    const float4* x4 = reinterpret_cast<const float4*>(x + (size_t)row * D);
    float4 a = x4[lane];
    float4 b = x4[lane + 32];

    float ss = a.x*a.x + a.y*a.y + a.z*a.z + a.w*a.w
             + b.x*b.x + b.y*b.y + b.z*b.z + b.w*b.w;
#pragma unroll
    for (int o = 16; o; o >>= 1) ss += __shfl_xor_sync(0xffffffffu, ss, o);

    float inv = 1.0f / fmaxf(sqrtf(ss), 1e-12f);
    a.x *= inv; a.y *= inv; a.z *= inv; a.w *= inv;
    b.x *= inv; b.y *= inv; b.z *= inv; b.w *= inv;

    __half2* h2 = reinterpret_cast<__half2*>(g_h4);
    size_t base = (size_t)row * (D / 2);

    h2[base + lane*2 + 0]      = __floats2half2_rn(a.x, a.y);
    h2[base + lane*2 + 1]      = __floats2half2_rn(a.z, a.w);
    h2[base + 64 + lane*2 + 0] = __floats2half2_rn(b.x, b.y);
    h2[base + 64 + lane*2 + 1] = __floats2half2_rn(b.z, b.w);

    if (lane == 0) { g_neg[row] = 0.0f; g_row[row] = 0.0f; g_cnt[row] = 0.0f; }
}

// Issue the 8 cp.async ops that fill one stage with chunk kc's two tiles.
__device__ __forceinline__ void issue_stage(uint32_t smb, int stage, int kc,
                                            int i0, int j0, int tid,
                                            const char* h_base)
{
    uint32_t sbase = smb + SM_TILE + stage * STAGE;
#pragma unroll
    for (int t = 0; t < 8; t++) {
        int idx = tid + t * 256;
        int mat = idx >> 10;          // 0 = A (rows i0), 1 = B (rows j0)
        int rem = idx & 1023;
        int row = rem >> 3;
        int c   = rem & 7;
        int grow = mat ? (j0 + row) : (i0 + row);
        const char* src = h_base + (size_t)grow * 512 + kc * 128 + c * 16;
        uint32_t dst = sbase + mat * TBYTES + row * TSTRIDE + c * 16;
        CP_ASYNC16(dst, src);
    }
    CP_COMMIT();
}

// ---------------------------------------------------------------------------
// Pass 1: single fp16 GEMM (128x128 tile), exp-mask neg sums, sim tile cached.
// 8 warps, warp tile 64x32; cp.async 2-stage pipeline; 2 CTAs/SM.
// ---------------------------------------------------------------------------
__global__ __launch_bounds__(256, 2) void pass1_kernel(int N)
{
    extern __shared__ char sm[];
    int bi = blockIdx.y, bj = blockIdx.x;
    if (bj < bi) return;

    int tid  = threadIdx.x;
    int wid  = tid >> 5;
    int lane = tid & 31;
    int i0 = bi * 128, j0 = bj * 128;
    bool offdiag = (bi != bj);
    uint32_t smb = smem_u32(sm);

    int* labA   = (int*)(sm + SM_LABA);
    int* labB   = (int*)(sm + SM_LABB);
    float* srow = (float*)(sm + SM_SROW);
    float* scol = (float*)(sm + SM_SCOL);

    const char* h_base = (const char*)g_h4;

    issue_stage(smb, 0, 0, i0, j0, tid, h_base);

    if (tid < 128) {
        labA[tid] = g_lab[i0 + tid];
        labB[tid] = g_lab[j0 + tid];
        srow[tid] = 0.0f; scol[tid] = 0.0f;
    }

    int wm0 = (wid & 1) * 64;
    int wn0 = (wid >> 1) * 32;

    float acc[4][4][4];
#pragma unroll
    for (int fm = 0; fm < 4; fm++)
#pragma unroll
        for (int fn = 0; fn < 4; fn++)
#pragma unroll
            for (int k = 0; k < 4; k++) acc[fm][fn][k] = 0.0f;

    int a_row = lane & 15;
    int a_kb  = (lane >> 4) * 16;
    int b_row = lane & 7;
    int b_kb  = ((lane >> 3) & 1) * 16;

#pragma unroll
    for (int kc = 0; kc < 4; kc++) {
        int s = kc & 1;
        CP_WAIT0();
        __syncthreads();
        if (kc < 3)
            issue_stage(smb, s ^ 1, kc + 1, i0, j0, tid, h_base);

        uint32_t off_a = SM_TILE + s * STAGE;
#pragma unroll
        for (int ks = 0; ks < 4; ks++) {
            uint32_t af[4][4], bf[4][2];
#pragma unroll
            for (int fm = 0; fm < 4; fm++) {
                uint32_t ra = smb + off_a + (wm0 + fm*16 + a_row) * TSTRIDE + ks*32 + a_kb;
                LDSM_X4(af[fm][0], af[fm][1], af[fm][2], af[fm][3], ra);
            }
#pragma unroll
            for (int fn = 0; fn < 4; fn++) {
                uint32_t rb = smb + off_a + TBYTES + (wn0 + fn*8 + b_row) * TSTRIDE + ks*32 + b_kb;
                LDSM_X2(bf[fn][0], bf[fn][1], rb);
            }
#pragma unroll
            for (int fm = 0; fm < 4; fm++)
#pragma unroll
                for (int fn = 0; fn < 4; fn++)
                    MMAF16(acc[fm][fn], af[fm][0],af[fm][1],af[fm][2],af[fm][3],
                           bf[fn][0], bf[fn][1]);
        }
        __syncthreads();
    }

    // store raw sim tile (thread-linear: [tid][fm*4+fn] float4) — coalesced STG.128
    {
        int T = N >> 7;
        int tidx = bi * (2*T - bi + 1) / 2 + (bj - bi);
        float4* dst = g_sim4 + ((size_t)tidx << 12) + tid * 16;
#pragma unroll
        for (int fm = 0; fm < 4; fm++)
#pragma unroll
            for (int fn = 0; fn < 4; fn++)
                dst[fm*4 + fn] = make_float4(acc[fm][fn][0], acc[fm][fn][1],
                                             acc[fm][fn][2], acc[fm][fn][3]);
    }

    // ---- epilogue: masked exp, row + col negative sums ----
    int g  = lane >> 2;
    int tg = lane & 3;

    int la8[8], lb8[8];
#pragma unroll
    for (int fm = 0; fm < 4; fm++)
#pragma unroll
        for (int h = 0; h < 2; h++)
            la8[fm*2+h] = labA[wm0 + fm*16 + g + h*8];
#pragma unroll
    for (int fn = 0; fn < 4; fn++)
#pragma unroll
        for (int p = 0; p < 2; p++)
            lb8[fn*2+p] = labB[wn0 + fn*8 + tg*2 + p];

    float rowa[8] = {0,0,0,0,0,0,0,0};
    float cola[8] = {0,0,0,0,0,0,0,0};

#pragma unroll
    for (int fm = 0; fm < 4; fm++)
#pragma unroll
        for (int fn = 0; fn < 4; fn++)
#pragma unroll
            for (int k = 0; k < 4; k++) {
                int h = k >> 1, p = k & 1;
                int ri = fm*2 + h, ci = fn*2 + p;
                if (la8[ri] != lb8[ci]) {
                    float e = __expf(acc[fm][fn][k] * INV_T);
                    rowa[ri] += e;
                    cola[ci] += e;
                }
            }

#pragma unroll
    for (int r = 0; r < 8; r++) {
        rowa[r] += __shfl_xor_sync(0xffffffffu, rowa[r], 1);
        rowa[r] += __shfl_xor_sync(0xffffffffu, rowa[r], 2);
        cola[r] += __shfl_xor_sync(0xffffffffu, cola[r], 4);
        cola[r] += __shfl_xor_sync(0xffffffffu, cola[r], 8);
        cola[r] += __shfl_xor_sync(0xffffffffu, cola[r], 16);
    }

    if (tg == 0) {
#pragma unroll
        for (int ri = 0; ri < 8; ri++) {
            int r = wm0 + (ri >> 1)*16 + g + (ri & 1)*8;
            atomicAdd(&srow[r], rowa[ri]);
        }
    }
    if (g == 0) {
#pragma unroll
        for (int ci = 0; ci < 8; ci++) {
            int c = wn0 + (ci >> 1)*8 + tg*2 + (ci & 1);
            atomicAdd(&scol[c], cola[ci]);
        }
    }
    __syncthreads();

    if (tid < 128) {
        atomicAdd(&g_neg[i0 + tid], srow[tid]);
        if (offdiag) atomicAdd(&g_neg[j0 + tid], scol[tid]);
    }
}

// ---------------------------------------------------------------------------
// Pass 2 (lite): no GEMM. Reads cached sim tile, positive-pair loss + counts.
// ---------------------------------------------------------------------------
__global__ __launch_bounds__(256) void pass2_kernel(int N)
{
    __shared__ int   labA[128], labB[128];
    __shared__ float negA[128], negB[128];
    __shared__ float srow[128], scol[128], scnr[128], scnc[128];

    int bi = blockIdx.y, bj = blockIdx.x;
    if (bj < bi) return;

    int tid  = threadIdx.x;
    int wid  = tid >> 5;
    int lane = tid & 31;
    int i0 = bi * 128, j0 = bj * 128;
    bool offdiag = (bi != bj);

    if (tid < 128) {
        labA[tid] = g_lab[i0 + tid];
        labB[tid] = g_lab[j0 + tid];
        negA[tid] = g_neg[i0 + tid];
        negB[tid] = g_neg[j0 + tid];
        srow[tid] = 0.0f; scol[tid] = 0.0f;
        scnr[tid] = 0.0f; scnc[tid] = 0.0f;
    }
    __syncthreads();

    int wm0 = (wid & 1) * 64;
    int wn0 = (wid >> 1) * 32;
    int g   = lane >> 2;
    int tg  = lane & 3;

    int T = N >> 7;
    int tidx = bi * (2*T - bi + 1) / 2 + (bj - bi);
    const float4* src = g_sim4 + ((size_t)tidx << 12) + tid * 16;

    int   la8[8], lb8[8];
    float na8[8], nb8[8];
#pragma unroll
    for (int fm = 0; fm < 4; fm++)
#pragma unroll
        for (int h = 0; h < 2; h++) {
            int r = wm0 + fm*16 + g + h*8;
            la8[fm*2+h] = labA[r];
            na8[fm*2+h] = negA[r];
        }
#pragma unroll
    for (int fn = 0; fn < 4; fn++)
#pragma unroll
        for (int p = 0; p < 2; p++) {
            int c = wn0 + fn*8 + tg*2 + p;
            lb8[fn*2+p] = labB[c];
            nb8[fn*2+p] = negB[c];
        }

    float rowa[8] = {0,0,0,0,0,0,0,0};
    float cola[8] = {0,0,0,0,0,0,0,0};
    float rowc[8] = {0,0,0,0,0,0,0,0};
    float colc[8] = {0,0,0,0,0,0,0,0};

#pragma unroll
    for (int fm = 0; fm < 4; fm++)
#pragma unroll
        for (int fn = 0; fn < 4; fn++) {
            float4 v = src[fm*4 + fn];
            float sv4[4] = {v.x, v.y, v.z, v.w};
#pragma unroll
            for (int k = 0; k < 4; k++) {
                int h = k >> 1, p = k & 1;
                int ri = fm*2 + h, ci = fn*2 + p;
                int grow = i0 + wm0 + fm*16 + g + h*8;
                int gcol = j0 + wn0 + fn*8 + tg*2 + p;
                if (la8[ri] == lb8[ci] && grow != gcol) {
                    float xm = __expf(-sv4[k] * INV_T);
                    rowa[ri] += __logf(fmaf(na8[ri], xm, 1.0f));
                    rowc[ri] += 1.0f;
                    cola[ci] += __logf(fmaf(nb8[ci], xm, 1.0f));
                    colc[ci] += 1.0f;
                }
            }
        }

#pragma unroll
    for (int r = 0; r < 8; r++) {
        rowa[r] += __shfl_xor_sync(0xffffffffu, rowa[r], 1);
        rowa[r] += __shfl_xor_sync(0xffffffffu, rowa[r], 2);
        rowc[r] += __shfl_xor_sync(0xffffffffu, rowc[r], 1);
        rowc[r] += __shfl_xor_sync(0xffffffffu, rowc[r], 2);
        cola[r] += __shfl_xor_sync(0xffffffffu, cola[r], 4);
        cola[r] += __shfl_xor_sync(0xffffffffu, cola[r], 8);
        cola[r] += __shfl_xor_sync(0xffffffffu, cola[r], 16);
        colc[r] += __shfl_xor_sync(0xffffffffu, colc[r], 4);
        colc[r] += __shfl_xor_sync(0xffffffffu, colc[r], 8);
        colc[r] += __shfl_xor_sync(0xffffffffu, colc[r], 16);
    }

    if (tg == 0) {
#pragma unroll
        for (int ri = 0; ri < 8; ri++) {
            int r = wm0 + (ri >> 1)*16 + g + (ri & 1)*8;
            atomicAdd(&srow[r], rowa[ri]);
            atomicAdd(&scnr[r], rowc[ri]);
        }
    }
    if (g == 0) {
#pragma unroll
        for (int ci = 0; ci < 8; ci++) {
            int c = wn0 + (ci >> 1)*8 + tg*2 + (ci & 1);
            atomicAdd(&scol[c], cola[ci]);
            atomicAdd(&scnc[c], colc[ci]);
        }
    }
    __syncthreads();

    if (tid < 128) {
        atomicAdd(&g_row[i0 + tid], srow[tid]);
        atomicAdd(&g_cnt[i0 + tid], scnr[tid]);
        if (offdiag) {
            atomicAdd(&g_row[j0 + tid], scol[tid]);
            atomicAdd(&g_cnt[j0 + tid], scnc[tid]);
        }
    }
}

// ---------------------------------------------------------------------------
__global__ void final_kernel(float* __restrict__ out, int N)
{
    __shared__ float sred[1024];
    __shared__ int   ired[1024];
    int tid = threadIdx.x;

    float sum = 0.0f; int vc = 0;
    for (int i = tid; i < N; i += 1024) {
        float c = g_cnt[i];
        if (c > 0.5f) { sum += g_row[i] / c; vc++; }
    }
    sred[tid] = sum; ired[tid] = vc;
    __syncthreads();
    for (int s = 512; s; s >>= 1) {
        if (tid < s) { sred[tid] += sred[tid + s]; ired[tid] += ired[tid + s]; }
        __syncthreads();
    }
    if (tid == 0) out[0] = (ired[0] > 0) ? sred[0] / (float)ired[0] : 0.0f;
}

// ---------------------------------------------------------------------------
extern "C" void kernel_launch(void* const* d_in, const int* in_sizes, int n_in,
                              void* d_out, int out_size)
{
    const float*        x   = (const float*)d_in[0];
    const unsigned int* lv  = (const unsigned int*)d_in[1];
    float*              out = (float*)d_out;

    int N = in_sizes[1];
    if (N > NMAX) N = NMAX;

    cudaFuncSetAttribute(pass1_kernel, cudaFuncAttributeMaxDynamicSharedMemorySize, SMEM_TOTAL);

    lab_kernel<<<1, 1024>>>(lv, N);
    prep_kernel<<<(N + 7) / 8, 256>>>(x, N);

    int T = N / 128;
    dim3 grid(T, T);
    pass1_kernel<<<grid, 256, SMEM_TOTAL>>>(N);
    pass2_kernel<<<grid, 256>>>(N);

    final_kernel<<<1, 1024>>>(out, N);
}

// round 15
// speedup vs baseline: 7.5730x; 1.3590x over previous
#include <cuda_runtime.h>
#include <cuda_fp16.h>
#include <stdint.h>

// SupervisedContrastiveLoss on GB300 (sm_103) — single fp16 mma.sync GEMM.
// R14 OOM'd (136MB fp32 sim cache + tight container). This round: sim cache
// stored as fp16 (68MB, precision margin >50x) AND frag-major layout so each
// warp load/store is fully coalesced (fixes R13's L1=76.6% replay bound).
//   h = x/||x||  (stored fp16)
//   pass1: s = h*h^T (fp32 accum); neg_sum[i] = sum_{lab_j != lab_i} exp(s/T);
//          sim tiles cached fp16 (frag-major, coalesced)
//   pass2: row_sum[i] = sum_{lab_j==lab_i, j!=i} log(1+neg_sum[i]*exp(-s/T))
//   out = mean over valid rows of row_sum/pos_cnt
// Symmetric: tiles bj >= bi only; off-diag tiles feed row and col accumulators.

#define NMAX 8192
#define D    256
#define INV_T 14.285714285714285714f
#define TMAXT (NMAX / 128)                     // 64 tile-rows
#define NTILES (TMAXT * (TMAXT + 1) / 2)       // 2080 upper-tri tiles

__device__ uint4 g_h4[NMAX * D * 2 / 16];      // fp16 [NMAX][D]
__device__ uint2 g_simh[(size_t)NTILES * 4096];   // 68MB fp16 sim cache, frag-major
__device__ float g_neg[NMAX];
__device__ float g_row[NMAX];
__device__ float g_cnt[NMAX];
__device__ int   g_lab[NMAX];

// ---------------- PTX helpers (sm_80-era, valid on plain sm_103) ------------
__device__ __forceinline__ uint32_t smem_u32(const void* p) {
    uint32_t a;
    asm("{ .reg .u64 t; cvta.to.shared.u64 t, %1; cvt.u32.u64 %0, t; }" : "=r"(a) : "l"(p));
    return a;
}

#define CP_ASYNC16(dst, src) \
    asm volatile("cp.async.cg.shared.global [%0], [%1], 16;" :: "r"(dst), "l"(src) : "memory")
#define CP_COMMIT() asm volatile("cp.async.commit_group;" ::: "memory")
#define CP_WAIT0()  asm volatile("cp.async.wait_group 0;" ::: "memory")

#define LDSM_X4(r0,r1,r2,r3,addr) \
    asm volatile("ldmatrix.sync.aligned.m8n8.x4.shared.b16 {%0,%1,%2,%3}, [%4];" \
        : "=r"(r0),"=r"(r1),"=r"(r2),"=r"(r3) : "r"(addr))
#define LDSM_X2(r0,r1,addr) \
    asm volatile("ldmatrix.sync.aligned.m8n8.x2.shared.b16 {%0,%1}, [%2];" \
        : "=r"(r0),"=r"(r1) : "r"(addr))
#define MMAF16(d,a0,a1,a2,a3,b0,b1) \
    asm volatile("mma.sync.aligned.m16n8k16.row.col.f32.f16.f16.f32 " \
        "{%0,%1,%2,%3}, {%4,%5,%6,%7}, {%8,%9}, {%0,%1,%2,%3};" \
        : "+f"((d)[0]),"+f"((d)[1]),"+f"((d)[2]),"+f"((d)[3]) \
        : "r"(a0),"r"(a1),"r"(a2),"r"(a3),"r"(b0),"r"(b1))

// -------------------- dynamic SMEM layout for pass1 (bytes) -----------------
#define SM_LABA   0        // int[128]
#define SM_LABB   512
#define SM_SROW   1024     // float[128]
#define SM_SCOL   1536
#define SM_TILE   2048
#define TSTRIDE   144      // 128B data + 16B pad -> ldmatrix phase covers all 32 banks
#define TBYTES    (128 * TSTRIDE)        // 18432
#define STAGE     (2 * TBYTES)           // 36864 per stage (A|B)
#define SMEM_TOTAL (SM_TILE + 2 * STAGE) // 75776 -> 2 CTAs/SM

// ---------------------------------------------------------------------------
// Label ingest, robust to int32 vs int64 storage (equality-only semantics).
// ---------------------------------------------------------------------------
__global__ void lab_kernel(const unsigned int* __restrict__ v, int N)
{
    __shared__ int s_or[1024];
    int tid = threadIdx.x;
    unsigned int o = 0;
    for (int i = 2 * tid + 1; i < N; i += 2048) o |= v[i];
    s_or[tid] = (o != 0);
    __syncthreads();
    for (int s = 512; s; s >>= 1) { if (tid < s) s_or[tid] |= s_or[tid + s]; __syncthreads(); }
    int is32 = s_or[0];
    for (int i = tid; i < N; i += 1024)
        g_lab[i] = is32 ? (int)v[i] : (int)v[2 * i];
}

// ---------------------------------------------------------------------------
// Normalize + fp16 convert. 256 threads = 8 warps, one warp per row.
// ---------------------------------------------------------------------------
__global__ __launch_bounds__(256) void prep_kernel(const float* __restrict__ x, int N)
{
    int row  = blockIdx.x * 8 + (threadIdx.x >> 5);
    if (row >= N) return;
    int lane = threadIdx.x & 31;

    const float4* x4 = reinterpret_cast<const float4*>(x + (size_t)row * D);
    float4 a = x4[lane];
    float4 b = x4[lane + 32];

    float ss = a.x*a.x + a.y*a.y + a.z*a.z + a.w*a.w
             + b.x*b.x + b.y*b.y + b.z*b.z + b.w*b.w;
#pragma unroll
    for (int o = 16; o; o >>= 1) ss += __shfl_xor_sync(0xffffffffu, ss, o);

    float inv = 1.0f / fmaxf(sqrtf(ss), 1e-12f);
    a.x *= inv; a.y *= inv; a.z *= inv; a.w *= inv;
    b.x *= inv; b.y *= inv; b.z *= inv; b.w *= inv;

    __half2* h2 = reinterpret_cast<__half2*>(g_h4);
    size_t base = (size_t)row * (D / 2);

    h2[base + lane*2 + 0]      = __floats2half2_rn(a.x, a.y);
    h2[base + lane*2 + 1]      = __floats2half2_rn(a.z, a.w);
    h2[base + 64 + lane*2 + 0] = __floats2half2_rn(b.x, b.y);
    h2[base + 64 + lane*2 + 1] = __floats2half2_rn(b.z, b.w);

    if (lane == 0) { g_neg[row] = 0.0f; g_row[row] = 0.0f; g_cnt[row] = 0.0f; }
}

// Issue the 8 cp.async ops that fill one stage with chunk kc's two tiles.
__device__ __forceinline__ void issue_stage(uint32_t smb, int stage, int kc,
                                            int i0, int j0, int tid,
                                            const char* h_base)
{
    uint32_t sbase = smb + SM_TILE + stage * STAGE;
#pragma unroll
    for (int t = 0; t < 8; t++) {
        int idx = tid + t * 256;
        int mat = idx >> 10;          // 0 = A (rows i0), 1 = B (rows j0)
        int rem = idx & 1023;
        int row = rem >> 3;
        int c   = rem & 7;
        int grow = mat ? (j0 + row) : (i0 + row);
        const char* src = h_base + (size_t)grow * 512 + kc * 128 + c * 16;
        uint32_t dst = sbase + mat * TBYTES + row * TSTRIDE + c * 16;
        CP_ASYNC16(dst, src);
    }
    CP_COMMIT();
}

// ---------------------------------------------------------------------------
// Pass 1: single fp16 GEMM (128x128 tile), exp-mask neg sums, sim tile cached.
// 8 warps, warp tile 64x32; cp.async 2-stage pipeline; 2 CTAs/SM.
// ---------------------------------------------------------------------------
__global__ __launch_bounds__(256, 2) void pass1_kernel(int N)
{
    extern __shared__ char sm[];
    int bi = blockIdx.y, bj = blockIdx.x;
    if (bj < bi) return;

    int tid  = threadIdx.x;
    int wid  = tid >> 5;
    int lane = tid & 31;
    int i0 = bi * 128, j0 = bj * 128;
    bool offdiag = (bi != bj);
    uint32_t smb = smem_u32(sm);

    int* labA   = (int*)(sm + SM_LABA);
    int* labB   = (int*)(sm + SM_LABB);
    float* srow = (float*)(sm + SM_SROW);
    float* scol = (float*)(sm + SM_SCOL);

    const char* h_base = (const char*)g_h4;

    issue_stage(smb, 0, 0, i0, j0, tid, h_base);

    if (tid < 128) {
        labA[tid] = g_lab[i0 + tid];
        labB[tid] = g_lab[j0 + tid];
        srow[tid] = 0.0f; scol[tid] = 0.0f;
    }

    int wm0 = (wid & 1) * 64;
    int wn0 = (wid >> 1) * 32;

    float acc[4][4][4];
#pragma unroll
    for (int fm = 0; fm < 4; fm++)
#pragma unroll
        for (int fn = 0; fn < 4; fn++)
#pragma unroll
            for (int k = 0; k < 4; k++) acc[fm][fn][k] = 0.0f;

    int a_row = lane & 15;
    int a_kb  = (lane >> 4) * 16;
    int b_row = lane & 7;
    int b_kb  = ((lane >> 3) & 1) * 16;

#pragma unroll
    for (int kc = 0; kc < 4; kc++) {
        int s = kc & 1;
        CP_WAIT0();
        __syncthreads();
        if (kc < 3)
            issue_stage(smb, s ^ 1, kc + 1, i0, j0, tid, h_base);

        uint32_t off_a = SM_TILE + s * STAGE;
#pragma unroll
        for (int ks = 0; ks < 4; ks++) {
            uint32_t af[4][4], bf[4][2];
#pragma unroll
            for (int fm = 0; fm < 4; fm++) {
                uint32_t ra = smb + off_a + (wm0 + fm*16 + a_row) * TSTRIDE + ks*32 + a_kb;
                LDSM_X4(af[fm][0], af[fm][1], af[fm][2], af[fm][3], ra);
            }
#pragma unroll
            for (int fn = 0; fn < 4; fn++) {
                uint32_t rb = smb + off_a + TBYTES + (wn0 + fn*8 + b_row) * TSTRIDE + ks*32 + b_kb;
                LDSM_X2(bf[fn][0], bf[fn][1], rb);
            }
#pragma unroll
            for (int fm = 0; fm < 4; fm++)
#pragma unroll
                for (int fn = 0; fn < 4; fn++)
                    MMAF16(acc[fm][fn], af[fm][0],af[fm][1],af[fm][2],af[fm][3],
                           bf[fn][0], bf[fn][1]);
        }
        __syncthreads();
    }

    // store sim tile fp16, FRAG-MAJOR: uint2 index = frag*256 + tid -> warp
    // writes 32 consecutive uint2 per STG.64 (2 lines, fully coalesced)
    {
        int T = N >> 7;
        int tidx = bi * (2*T - bi + 1) / 2 + (bj - bi);
        uint2* dst = g_simh + ((size_t)tidx << 12);
#pragma unroll
        for (int fm = 0; fm < 4; fm++)
#pragma unroll
            for (int fn = 0; fn < 4; fn++) {
                __half2 lo = __floats2half2_rn(acc[fm][fn][0], acc[fm][fn][1]);
                __half2 hi = __floats2half2_rn(acc[fm][fn][2], acc[fm][fn][3]);
                uint2 pk;
                pk.x = *reinterpret_cast<uint32_t*>(&lo);
                pk.y = *reinterpret_cast<uint32_t*>(&hi);
                dst[(fm*4 + fn) * 256 + tid] = pk;
            }
    }

    // ---- epilogue: masked exp, row + col negative sums ----
    int g  = lane >> 2;
    int tg = lane & 3;

    int la8[8], lb8[8];
#pragma unroll
    for (int fm = 0; fm < 4; fm++)
#pragma unroll
        for (int h = 0; h < 2; h++)
            la8[fm*2+h] = labA[wm0 + fm*16 + g + h*8];
#pragma unroll
    for (int fn = 0; fn < 4; fn++)
#pragma unroll
        for (int p = 0; p < 2; p++)
            lb8[fn*2+p] = labB[wn0 + fn*8 + tg*2 + p];

    float rowa[8] = {0,0,0,0,0,0,0,0};
    float cola[8] = {0,0,0,0,0,0,0,0};

#pragma unroll
    for (int fm = 0; fm < 4; fm++)
#pragma unroll
        for (int fn = 0; fn < 4; fn++)
#pragma unroll
            for (int k = 0; k < 4; k++) {
                int h = k >> 1, p = k & 1;
                int ri = fm*2 + h, ci = fn*2 + p;
                if (la8[ri] != lb8[ci]) {
                    float e = __expf(acc[fm][fn][k] * INV_T);
                    rowa[ri] += e;
                    cola[ci] += e;
                }
            }

#pragma unroll
    for (int r = 0; r < 8; r++) {
        rowa[r] += __shfl_xor_sync(0xffffffffu, rowa[r], 1);
        rowa[r] += __shfl_xor_sync(0xffffffffu, rowa[r], 2);
        cola[r] += __shfl_xor_sync(0xffffffffu, cola[r], 4);
        cola[r] += __shfl_xor_sync(0xffffffffu, cola[r], 8);
        cola[r] += __shfl_xor_sync(0xffffffffu, cola[r], 16);
    }

    if (tg == 0) {
#pragma unroll
        for (int ri = 0; ri < 8; ri++) {
            int r = wm0 + (ri >> 1)*16 + g + (ri & 1)*8;
            atomicAdd(&srow[r], rowa[ri]);
        }
    }
    if (g == 0) {
#pragma unroll
        for (int ci = 0; ci < 8; ci++) {
            int c = wn0 + (ci >> 1)*8 + tg*2 + (ci & 1);
            atomicAdd(&scol[c], cola[ci]);
        }
    }
    __syncthreads();

    if (tid < 128) {
        atomicAdd(&g_neg[i0 + tid], srow[tid]);
        if (offdiag) atomicAdd(&g_neg[j0 + tid], scol[tid]);
    }
}

// ---------------------------------------------------------------------------
// Pass 2 (lite): no GEMM. Reads fp16 sim tile (frag-major, coalesced),
// positive-pair loss + counts.
// ---------------------------------------------------------------------------
__global__ __launch_bounds__(256) void pass2_kernel(int N)
{
    __shared__ int   labA[128], labB[128];
    __shared__ float negA[128], negB[128];
    __shared__ float srow[128], scol[128], scnr[128], scnc[128];

    int bi = blockIdx.y, bj = blockIdx.x;
    if (bj < bi) return;

    int tid  = threadIdx.x;
    int wid  = tid >> 5;
    int lane = tid & 31;
    int i0 = bi * 128, j0 = bj * 128;
    bool offdiag = (bi != bj);

    if (tid < 128) {
        labA[tid] = g_lab[i0 + tid];
        labB[tid] = g_lab[j0 + tid];
        negA[tid] = g_neg[i0 + tid];
        negB[tid] = g_neg[j0 + tid];
        srow[tid] = 0.0f; scol[tid] = 0.0f;
        scnr[tid] = 0.0f; scnc[tid] = 0.0f;
    }
    __syncthreads();

    int wm0 = (wid & 1) * 64;
    int wn0 = (wid >> 1) * 32;
    int g   = lane >> 2;
    int tg  = lane & 3;

    int T = N >> 7;
    int tidx = bi * (2*T - bi + 1) / 2 + (bj - bi);
    const uint2* src = g_simh + ((size_t)tidx << 12);

    int   la8[8], lb8[8];
    float na8[8], nb8[8];
#pragma unroll
    for (int fm = 0; fm < 4; fm++)
#pragma unroll
        for (int h = 0; h < 2; h++) {
            int r = wm0 + fm*16 + g + h*8;
            la8[fm*2+h] = labA[r];
            na8[fm*2+h] = negA[r];
        }
#pragma unroll
    for (int fn = 0; fn < 4; fn++)
#pragma unroll
        for (int p = 0; p < 2; p++) {
            int c = wn0 + fn*8 + tg*2 + p;
            lb8[fn*2+p] = labB[c];
            nb8[fn*2+p] = negB[c];
        }

    float rowa[8] = {0,0,0,0,0,0,0,0};
    float cola[8] = {0,0,0,0,0,0,0,0};
    float rowc[8] = {0,0,0,0,0,0,0,0};
    float colc[8] = {0,0,0,0,0,0,0,0};

#pragma unroll
    for (int fm = 0; fm < 4; fm++)
#pragma unroll
        for (int fn = 0; fn < 4; fn++) {
            uint2 pk = src[(fm*4 + fn) * 256 + tid];
            __half2 lo = *reinterpret_cast<__half2*>(&pk.x);
            __half2 hi = *reinterpret_cast<__half2*>(&pk.y);
            float2 f01 = __half22float2(lo);
            float2 f23 = __half22float2(hi);
            float sv4[4] = {f01.x, f01.y, f23.x, f23.y};
#pragma unroll
            for (int k = 0; k < 4; k++) {
                int h = k >> 1, p = k & 1;
                int ri = fm*2 + h, ci = fn*2 + p;
                int grow = i0 + wm0 + fm*16 + g + h*8;
                int gcol = j0 + wn0 + fn*8 + tg*2 + p;
                if (la8[ri] == lb8[ci] && grow != gcol) {
                    float xm = __expf(-sv4[k] * INV_T);
                    rowa[ri] += __logf(fmaf(na8[ri], xm, 1.0f));
                    rowc[ri] += 1.0f;
                    cola[ci] += __logf(fmaf(nb8[ci], xm, 1.0f));
                    colc[ci] += 1.0f;
                }
            }
        }

#pragma unroll
    for (int r = 0; r < 8; r++) {
        rowa[r] += __shfl_xor_sync(0xffffffffu, rowa[r], 1);
        rowa[r] += __shfl_xor_sync(0xffffffffu, rowa[r], 2);
        rowc[r] += __shfl_xor_sync(0xffffffffu, rowc[r], 1);
        rowc[r] += __shfl_xor_sync(0xffffffffu, rowc[r], 2);
        cola[r] += __shfl_xor_sync(0xffffffffu, cola[r], 4);
        cola[r] += __shfl_xor_sync(0xffffffffu, cola[r], 8);
        cola[r] += __shfl_xor_sync(0xffffffffu, cola[r], 16);
        colc[r] += __shfl_xor_sync(0xffffffffu, colc[r], 4);
        colc[r] += __shfl_xor_sync(0xffffffffu, colc[r], 8);
        colc[r] += __shfl_xor_sync(0xffffffffu, colc[r], 16);
    }

    if (tg == 0) {
#pragma unroll
        for (int ri = 0; ri < 8; ri++) {
            int r = wm0 + (ri >> 1)*16 + g + (ri & 1)*8;
            atomicAdd(&srow[r], rowa[ri]);
            atomicAdd(&scnr[r], rowc[ri]);
        }
    }
    if (g == 0) {
#pragma unroll
        for (int ci = 0; ci < 8; ci++) {
            int c = wn0 + (ci >> 1)*8 + tg*2 + (ci & 1);
            atomicAdd(&scol[c], cola[ci]);
            atomicAdd(&scnc[c], colc[ci]);
        }
    }
    __syncthreads();

    if (tid < 128) {
        atomicAdd(&g_row[i0 + tid], srow[tid]);
        atomicAdd(&g_cnt[i0 + tid], scnr[tid]);
        if (offdiag) {
            atomicAdd(&g_row[j0 + tid], scol[tid]);
            atomicAdd(&g_cnt[j0 + tid], scnc[tid]);
        }
    }
}

// ---------------------------------------------------------------------------
__global__ void final_kernel(float* __restrict__ out, int N)
{
    __shared__ float sred[1024];
    __shared__ int   ired[1024];
    int tid = threadIdx.x;

    float sum = 0.0f; int vc = 0;
    for (int i = tid; i < N; i += 1024) {
        float c = g_cnt[i];
        if (c > 0.5f) { sum += g_row[i] / c; vc++; }
    }
    sred[tid] = sum; ired[tid] = vc;
    __syncthreads();
    for (int s = 512; s; s >>= 1) {
        if (tid < s) { sred[tid] += sred[tid + s]; ired[tid] += ired[tid + s]; }
        __syncthreads();
    }
    if (tid == 0) out[0] = (ired[0] > 0) ? sred[0] / (float)ired[0] : 0.0f;
}

// ---------------------------------------------------------------------------
extern "C" void kernel_launch(void* const* d_in, const int* in_sizes, int n_in,
                              void* d_out, int out_size)
{
    const float*        x   = (const float*)d_in[0];
    const unsigned int* lv  = (const unsigned int*)d_in[1];
    float*              out = (float*)d_out;

    int N = in_sizes[1];
    if (N > NMAX) N = NMAX;

    cudaFuncSetAttribute(pass1_kernel, cudaFuncAttributeMaxDynamicSharedMemorySize, SMEM_TOTAL);

    lab_kernel<<<1, 1024>>>(lv, N);
    prep_kernel<<<(N + 7) / 8, 256>>>(x, N);

    int T = N / 128;
    dim3 grid(T, T);
    pass1_kernel<<<grid, 256, SMEM_TOTAL>>>(N);
    pass2_kernel<<<grid, 256>>>(N);

    final_kernel<<<1, 1024>>>(out, N);
}

// round 16
// speedup vs baseline: 7.7623x; 1.0250x over previous
#include <cuda_runtime.h>
#include <cuda_fp16.h>
#include <stdint.h>

// SupervisedContrastiveLoss on GB300 (sm_103) — single fp16 mma.sync GEMM.
// R15 lesson: pass2 spent ~24us in MUFU (expf + 2x logf per positive pair).
// This round: log(1+na*e^{-s/T}) = log(na) - s/T + log1p(e^{s/T}/na); the
// log(na) part factors into final_kernel (once per row: + cnt*log(neg)), and
// log1p(u) with u<=0.012 is a 3-term Taylor (pure FMA). Pass2: 1 EX2/element.
//   h = x/||x||  (stored fp16)
//   pass1: s = h*h^T (fp32 accum); neg_sum[i] = sum_{lab_j != lab_i} exp(s/T);
//          sim tiles cached fp16 (frag-major, coalesced)
//   pass2: row partial  += log1p(es*rna) - s/T  over positives (and col side)
//   final: row_loss = g_row/cnt + log(g_neg)
// Symmetric: tiles bj >= bi only; off-diag tiles feed row and col accumulators.

#define NMAX 8192
#define D    256
#define INV_T 14.285714285714285714f
#define TMAXT (NMAX / 128)                     // 64 tile-rows
#define NTILES (TMAXT * (TMAXT + 1) / 2)       // 2080 upper-tri tiles

__device__ uint4 g_h4[NMAX * D * 2 / 16];      // fp16 [NMAX][D]
__device__ uint2 g_simh[(size_t)NTILES * 4096];   // 68MB fp16 sim cache, frag-major
__device__ float g_neg[NMAX];
__device__ float g_row[NMAX];
__device__ float g_cnt[NMAX];
__device__ int   g_lab[NMAX];

// ---------------- PTX helpers (sm_80-era, valid on plain sm_103) ------------
__device__ __forceinline__ uint32_t smem_u32(const void* p) {
    uint32_t a;
    asm("{ .reg .u64 t; cvta.to.shared.u64 t, %1; cvt.u32.u64 %0, t; }" : "=r"(a) : "l"(p));
    return a;
}

#define CP_ASYNC16(dst, src) \
    asm volatile("cp.async.cg.shared.global [%0], [%1], 16;" :: "r"(dst), "l"(src) : "memory")
#define CP_COMMIT() asm volatile("cp.async.commit_group;" ::: "memory")
#define CP_WAIT0()  asm volatile("cp.async.wait_group 0;" ::: "memory")

#define LDSM_X4(r0,r1,r2,r3,addr) \
    asm volatile("ldmatrix.sync.aligned.m8n8.x4.shared.b16 {%0,%1,%2,%3}, [%4];" \
        : "=r"(r0),"=r"(r1),"=r"(r2),"=r"(r3) : "r"(addr))
#define LDSM_X2(r0,r1,addr) \
    asm volatile("ldmatrix.sync.aligned.m8n8.x2.shared.b16 {%0,%1}, [%2];" \
        : "=r"(r0),"=r"(r1) : "r"(addr))
#define MMAF16(d,a0,a1,a2,a3,b0,b1) \
    asm volatile("mma.sync.aligned.m16n8k16.row.col.f32.f16.f16.f32 " \
        "{%0,%1,%2,%3}, {%4,%5,%6,%7}, {%8,%9}, {%0,%1,%2,%3};" \
        : "+f"((d)[0]),"+f"((d)[1]),"+f"((d)[2]),"+f"((d)[3]) \
        : "r"(a0),"r"(a1),"r"(a2),"r"(a3),"r"(b0),"r"(b1))

// -------------------- dynamic SMEM layout for pass1 (bytes) -----------------
#define SM_LABA   0        // int[128]
#define SM_LABB   512
#define SM_SROW   1024     // float[128]
#define SM_SCOL   1536
#define SM_TILE   2048
#define TSTRIDE   144      // 128B data + 16B pad -> ldmatrix phase covers all 32 banks
#define TBYTES    (128 * TSTRIDE)        // 18432
#define STAGE     (2 * TBYTES)           // 36864 per stage (A|B)
#define SMEM_TOTAL (SM_TILE + 2 * STAGE) // 75776 -> 2 CTAs/SM

// ---------------------------------------------------------------------------
// Label ingest, robust to int32 vs int64 storage (equality-only semantics).
// ---------------------------------------------------------------------------
__global__ void lab_kernel(const unsigned int* __restrict__ v, int N)
{
    __shared__ int s_or[1024];
    int tid = threadIdx.x;
    unsigned int o = 0;
    for (int i = 2 * tid + 1; i < N; i += 2048) o |= v[i];
    s_or[tid] = (o != 0);
    __syncthreads();
    for (int s = 512; s; s >>= 1) { if (tid < s) s_or[tid] |= s_or[tid + s]; __syncthreads(); }
    int is32 = s_or[0];
    for (int i = tid; i < N; i += 1024)
        g_lab[i] = is32 ? (int)v[i] : (int)v[2 * i];
}

// ---------------------------------------------------------------------------
// Normalize + fp16 convert. 256 threads = 8 warps, one warp per row.
// ---------------------------------------------------------------------------
__global__ __launch_bounds__(256) void prep_kernel(const float* __restrict__ x, int N)
{
    int row  = blockIdx.x * 8 + (threadIdx.x >> 5);
    if (row >= N) return;
    int lane = threadIdx.x & 31;

    const float4* x4 = reinterpret_cast<const float4*>(x + (size_t)row * D);
    float4 a = x4[lane];
    float4 b = x4[lane + 32];

    float ss = a.x*a.x + a.y*a.y + a.z*a.z + a.w*a.w
             + b.x*b.x + b.y*b.y + b.z*b.z + b.w*b.w;
#pragma unroll
    for (int o = 16; o; o >>= 1) ss += __shfl_xor_sync(0xffffffffu, ss, o);

    float inv = 1.0f / fmaxf(sqrtf(ss), 1e-12f);
    a.x *= inv; a.y *= inv; a.z *= inv; a.w *= inv;
    b.x *= inv; b.y *= inv; b.z *= inv; b.w *= inv;

    __half2* h2 = reinterpret_cast<__half2*>(g_h4);
    size_t base = (size_t)row * (D / 2);

    h2[base + lane*2 + 0]      = __floats2half2_rn(a.x, a.y);
    h2[base + lane*2 + 1]      = __floats2half2_rn(a.z, a.w);
    h2[base + 64 + lane*2 + 0] = __floats2half2_rn(b.x, b.y);
    h2[base + 64 + lane*2 + 1] = __floats2half2_rn(b.z, b.w);

    if (lane == 0) { g_neg[row] = 0.0f; g_row[row] = 0.0f; g_cnt[row] = 0.0f; }
}

// Issue the 8 cp.async ops that fill one stage with chunk kc's two tiles.
__device__ __forceinline__ void issue_stage(uint32_t smb, int stage, int kc,
                                            int i0, int j0, int tid,
                                            const char* h_base)
{
    uint32_t sbase = smb + SM_TILE + stage * STAGE;
#pragma unroll
    for (int t = 0; t < 8; t++) {
        int idx = tid + t * 256;
        int mat = idx >> 10;          // 0 = A (rows i0), 1 = B (rows j0)
        int rem = idx & 1023;
        int row = rem >> 3;
        int c   = rem & 7;
        int grow = mat ? (j0 + row) : (i0 + row);
        const char* src = h_base + (size_t)grow * 512 + kc * 128 + c * 16;
        uint32_t dst = sbase + mat * TBYTES + row * TSTRIDE + c * 16;
        CP_ASYNC16(dst, src);
    }
    CP_COMMIT();
}

// ---------------------------------------------------------------------------
// Pass 1: single fp16 GEMM (128x128 tile), exp-mask neg sums, sim tile cached.
// 8 warps, warp tile 64x32; cp.async 2-stage pipeline; 2 CTAs/SM.
// ---------------------------------------------------------------------------
__global__ __launch_bounds__(256, 2) void pass1_kernel(int N)
{
    extern __shared__ char sm[];
    int bi = blockIdx.y, bj = blockIdx.x;
    if (bj < bi) return;

    int tid  = threadIdx.x;
    int wid  = tid >> 5;
    int lane = tid & 31;
    int i0 = bi * 128, j0 = bj * 128;
    bool offdiag = (bi != bj);
    uint32_t smb = smem_u32(sm);

    int* labA   = (int*)(sm + SM_LABA);
    int* labB   = (int*)(sm + SM_LABB);
    float* srow = (float*)(sm + SM_SROW);
    float* scol = (float*)(sm + SM_SCOL);

    const char* h_base = (const char*)g_h4;

    issue_stage(smb, 0, 0, i0, j0, tid, h_base);

    if (tid < 128) {
        labA[tid] = g_lab[i0 + tid];
        labB[tid] = g_lab[j0 + tid];
        srow[tid] = 0.0f; scol[tid] = 0.0f;
    }

    int wm0 = (wid & 1) * 64;
    int wn0 = (wid >> 1) * 32;

    float acc[4][4][4];
#pragma unroll
    for (int fm = 0; fm < 4; fm++)
#pragma unroll
        for (int fn = 0; fn < 4; fn++)
#pragma unroll
            for (int k = 0; k < 4; k++) acc[fm][fn][k] = 0.0f;

    int a_row = lane & 15;
    int a_kb  = (lane >> 4) * 16;
    int b_row = lane & 7;
    int b_kb  = ((lane >> 3) & 1) * 16;

#pragma unroll
    for (int kc = 0; kc < 4; kc++) {
        int s = kc & 1;
        CP_WAIT0();
        __syncthreads();
        if (kc < 3)
            issue_stage(smb, s ^ 1, kc + 1, i0, j0, tid, h_base);

        uint32_t off_a = SM_TILE + s * STAGE;
#pragma unroll
        for (int ks = 0; ks < 4; ks++) {
            uint32_t af[4][4], bf[4][2];
#pragma unroll
            for (int fm = 0; fm < 4; fm++) {
                uint32_t ra = smb + off_a + (wm0 + fm*16 + a_row) * TSTRIDE + ks*32 + a_kb;
                LDSM_X4(af[fm][0], af[fm][1], af[fm][2], af[fm][3], ra);
            }
#pragma unroll
            for (int fn = 0; fn < 4; fn++) {
                uint32_t rb = smb + off_a + TBYTES + (wn0 + fn*8 + b_row) * TSTRIDE + ks*32 + b_kb;
                LDSM_X2(bf[fn][0], bf[fn][1], rb);
            }
#pragma unroll
            for (int fm = 0; fm < 4; fm++)
#pragma unroll
                for (int fn = 0; fn < 4; fn++)
                    MMAF16(acc[fm][fn], af[fm][0],af[fm][1],af[fm][2],af[fm][3],
                           bf[fn][0], bf[fn][1]);
        }
        __syncthreads();
    }

    // store sim tile fp16, FRAG-MAJOR: uint2 index = frag*256 + tid -> warp
    // writes 32 consecutive uint2 per STG.64 (2 lines, fully coalesced)
    {
        int T = N >> 7;
        int tidx = bi * (2*T - bi + 1) / 2 + (bj - bi);
        uint2* dst = g_simh + ((size_t)tidx << 12);
#pragma unroll
        for (int fm = 0; fm < 4; fm++)
#pragma unroll
            for (int fn = 0; fn < 4; fn++) {
                __half2 lo = __floats2half2_rn(acc[fm][fn][0], acc[fm][fn][1]);
                __half2 hi = __floats2half2_rn(acc[fm][fn][2], acc[fm][fn][3]);
                uint2 pk;
                pk.x = *reinterpret_cast<uint32_t*>(&lo);
                pk.y = *reinterpret_cast<uint32_t*>(&hi);
                dst[(fm*4 + fn) * 256 + tid] = pk;
            }
    }

    // ---- epilogue: masked exp, row + col negative sums ----
    int g  = lane >> 2;
    int tg = lane & 3;

    int la8[8], lb8[8];
#pragma unroll
    for (int fm = 0; fm < 4; fm++)
#pragma unroll
        for (int h = 0; h < 2; h++)
            la8[fm*2+h] = labA[wm0 + fm*16 + g + h*8];
#pragma unroll
    for (int fn = 0; fn < 4; fn++)
#pragma unroll
        for (int p = 0; p < 2; p++)
            lb8[fn*2+p] = labB[wn0 + fn*8 + tg*2 + p];

    float rowa[8] = {0,0,0,0,0,0,0,0};
    float cola[8] = {0,0,0,0,0,0,0,0};

#pragma unroll
    for (int fm = 0; fm < 4; fm++)
#pragma unroll
        for (int fn = 0; fn < 4; fn++)
#pragma unroll
            for (int k = 0; k < 4; k++) {
                int h = k >> 1, p = k & 1;
                int ri = fm*2 + h, ci = fn*2 + p;
                if (la8[ri] != lb8[ci]) {
                    float e = __expf(acc[fm][fn][k] * INV_T);
                    rowa[ri] += e;
                    cola[ci] += e;
                }
            }

#pragma unroll
    for (int r = 0; r < 8; r++) {
        rowa[r] += __shfl_xor_sync(0xffffffffu, rowa[r], 1);
        rowa[r] += __shfl_xor_sync(0xffffffffu, rowa[r], 2);
        cola[r] += __shfl_xor_sync(0xffffffffu, cola[r], 4);
        cola[r] += __shfl_xor_sync(0xffffffffu, cola[r], 8);
        cola[r] += __shfl_xor_sync(0xffffffffu, cola[r], 16);
    }

    if (tg == 0) {
#pragma unroll
        for (int ri = 0; ri < 8; ri++) {
            int r = wm0 + (ri >> 1)*16 + g + (ri & 1)*8;
            atomicAdd(&srow[r], rowa[ri]);
        }
    }
    if (g == 0) {
#pragma unroll
        for (int ci = 0; ci < 8; ci++) {
            int c = wn0 + (ci >> 1)*8 + tg*2 + (ci & 1);
            atomicAdd(&scol[c], cola[ci]);
        }
    }
    __syncthreads();

    if (tid < 128) {
        atomicAdd(&g_neg[i0 + tid], srow[tid]);
        if (offdiag) atomicAdd(&g_neg[j0 + tid], scol[tid]);
    }
}

// ---------------------------------------------------------------------------
// Pass 2 (lite): no GEMM, no logf. Per positive element accumulates
//   log1p(es*rna) - s/T    (es = e^{s/T}, rna = 1/neg_row; cubic log1p)
// final_kernel re-adds cnt*log(neg) per row. 1 EX2 per element total.
// ---------------------------------------------------------------------------
__global__ __launch_bounds__(256) void pass2_kernel(int N)
{
    __shared__ int   labA[128], labB[128];
    __shared__ float rnaA[128], rnaB[128];
    __shared__ float srow[128], scol[128], scnr[128], scnc[128];

    int bi = blockIdx.y, bj = blockIdx.x;
    if (bj < bi) return;

    int tid  = threadIdx.x;
    int wid  = tid >> 5;
    int lane = tid & 31;
    int i0 = bi * 128, j0 = bj * 128;
    bool offdiag = (bi != bj);

    if (tid < 128) {
        labA[tid] = g_lab[i0 + tid];
        labB[tid] = g_lab[j0 + tid];
        rnaA[tid] = 1.0f / fmaxf(g_neg[i0 + tid], 1e-30f);
        rnaB[tid] = 1.0f / fmaxf(g_neg[j0 + tid], 1e-30f);
        srow[tid] = 0.0f; scol[tid] = 0.0f;
        scnr[tid] = 0.0f; scnc[tid] = 0.0f;
    }
    __syncthreads();

    int wm0 = (wid & 1) * 64;
    int wn0 = (wid >> 1) * 32;
    int g   = lane >> 2;
    int tg  = lane & 3;

    int T = N >> 7;
    int tidx = bi * (2*T - bi + 1) / 2 + (bj - bi);
    const uint2* src = g_simh + ((size_t)tidx << 12);

    int   la8[8], lb8[8];
    float na8[8], nb8[8];
#pragma unroll
    for (int fm = 0; fm < 4; fm++)
#pragma unroll
        for (int h = 0; h < 2; h++) {
            int r = wm0 + fm*16 + g + h*8;
            la8[fm*2+h] = labA[r];
            na8[fm*2+h] = rnaA[r];
        }
#pragma unroll
    for (int fn = 0; fn < 4; fn++)
#pragma unroll
        for (int p = 0; p < 2; p++) {
            int c = wn0 + fn*8 + tg*2 + p;
            lb8[fn*2+p] = labB[c];
            nb8[fn*2+p] = rnaB[c];
        }

    float rowa[8] = {0,0,0,0,0,0,0,0};
    float cola[8] = {0,0,0,0,0,0,0,0};
    float rowc[8] = {0,0,0,0,0,0,0,0};
    float colc[8] = {0,0,0,0,0,0,0,0};

#pragma unroll
    for (int fm = 0; fm < 4; fm++)
#pragma unroll
        for (int fn = 0; fn < 4; fn++) {
            uint2 pk = src[(fm*4 + fn) * 256 + tid];
            __half2 lo = *reinterpret_cast<__half2*>(&pk.x);
            __half2 hi = *reinterpret_cast<__half2*>(&pk.y);
            float2 f01 = __half22float2(lo);
            float2 f23 = __half22float2(hi);
            float sv4[4] = {f01.x, f01.y, f23.x, f23.y};
#pragma unroll
            for (int k = 0; k < 4; k++) {
                int h = k >> 1, p = k & 1;
                int ri = fm*2 + h, ci = fn*2 + p;
                int grow = i0 + wm0 + fm*16 + g + h*8;
                int gcol = j0 + wn0 + fn*8 + tg*2 + p;
                if (la8[ri] == lb8[ci] && grow != gcol) {
                    float sT = sv4[k] * INV_T;
                    float es = __expf(sT);
                    // row side: log1p(es*rna) - sT  (cubic log1p, u <= ~0.02)
                    float u  = es * na8[ri];
                    float pr = u * (1.0f - u * (0.5f - 0.33333333f * u));
                    rowa[ri] += pr - sT;
                    rowc[ri] += 1.0f;
                    // col side
                    float u2 = es * nb8[ci];
                    float pc = u2 * (1.0f - u2 * (0.5f - 0.33333333f * u2));
                    cola[ci] += pc - sT;
                    colc[ci] += 1.0f;
                }
            }
        }

#pragma unroll
    for (int r = 0; r < 8; r++) {
        rowa[r] += __shfl_xor_sync(0xffffffffu, rowa[r], 1);
        rowa[r] += __shfl_xor_sync(0xffffffffu, rowa[r], 2);
        rowc[r] += __shfl_xor_sync(0xffffffffu, rowc[r], 1);
        rowc[r] += __shfl_xor_sync(0xffffffffu, rowc[r], 2);
        cola[r] += __shfl_xor_sync(0xffffffffu, cola[r], 4);
        cola[r] += __shfl_xor_sync(0xffffffffu, cola[r], 8);
        cola[r] += __shfl_xor_sync(0xffffffffu, cola[r], 16);
        colc[r] += __shfl_xor_sync(0xffffffffu, colc[r], 4);
        colc[r] += __shfl_xor_sync(0xffffffffu, colc[r], 8);
        colc[r] += __shfl_xor_sync(0xffffffffu, colc[r], 16);
    }

    if (tg == 0) {
#pragma unroll
        for (int ri = 0; ri < 8; ri++) {
            int r = wm0 + (ri >> 1)*16 + g + (ri & 1)*8;
            atomicAdd(&srow[r], rowa[ri]);
            atomicAdd(&scnr[r], rowc[ri]);
        }
    }
    if (g == 0) {
#pragma unroll
        for (int ci = 0; ci < 8; ci++) {
            int c = wn0 + (ci >> 1)*8 + tg*2 + (ci & 1);
            atomicAdd(&scol[c], cola[ci]);
            atomicAdd(&scnc[c], colc[ci]);
        }
    }
    __syncthreads();

    if (tid < 128) {
        atomicAdd(&g_row[i0 + tid], srow[tid]);
        atomicAdd(&g_cnt[i0 + tid], scnr[tid]);
        if (offdiag) {
            atomicAdd(&g_row[j0 + tid], scol[tid]);
            atomicAdd(&g_cnt[j0 + tid], scnc[tid]);
        }
    }
}

// ---------------------------------------------------------------------------
// Final: row_loss = g_row/cnt + log(neg)  (the factored cnt*log(neg) term).
// ---------------------------------------------------------------------------
__global__ void final_kernel(float* __restrict__ out, int N)
{
    __shared__ float sred[1024];
    __shared__ int   ired[1024];
    int tid = threadIdx.x;

    float sum = 0.0f; int vc = 0;
    for (int i = tid; i < N; i += 1024) {
        float c = g_cnt[i];
        if (c > 0.5f) {
            sum += g_row[i] / c + logf(fmaxf(g_neg[i], 1e-30f));
            vc++;
        }
    }
    sred[tid] = sum; ired[tid] = vc;
    __syncthreads();
    for (int s = 512; s; s >>= 1) {
        if (tid < s) { sred[tid] += sred[tid + s]; ired[tid] += ired[tid + s]; }
        __syncthreads();
    }
    if (tid == 0) out[0] = (ired[0] > 0) ? sred[0] / (float)ired[0] : 0.0f;
}

// ---------------------------------------------------------------------------
extern "C" void kernel_launch(void* const* d_in, const int* in_sizes, int n_in,
                              void* d_out, int out_size)
{
    const float*        x   = (const float*)d_in[0];
    const unsigned int* lv  = (const unsigned int*)d_in[1];
    float*              out = (float*)d_out;

    int N = in_sizes[1];
    if (N > NMAX) N = NMAX;

    cudaFuncSetAttribute(pass1_kernel, cudaFuncAttributeMaxDynamicSharedMemorySize, SMEM_TOTAL);

    lab_kernel<<<1, 1024>>>(lv, N);
    prep_kernel<<<(N + 7) / 8, 256>>>(x, N);

    int T = N / 128;
    dim3 grid(T, T);
    pass1_kernel<<<grid, 256, SMEM_TOTAL>>>(N);
    pass2_kernel<<<grid, 256>>>(N);

    final_kernel<<<1, 1024>>>(out, N);
}

// round 17
// speedup vs baseline: 9.2129x; 1.1869x over previous
#include <cuda_runtime.h>
#include <cuda_fp16.h>
#include <stdint.h>

// SupervisedContrastiveLoss on GB300 (sm_103) — FUSED single-pass version.
// R16 lesson: pass2 was issue-bound bookkeeping; but log1p Taylor terms are
// separable in neg: sum_pos log1p(es/neg) ~ P1/neg - P2/(2 neg^2), with
// P1=sum es, P2=sum es^2 independent of neg. So pass1's epilogue accumulates
// per-row/col: {sum es}_negatives, P1, P2, S=sum s/T, C over positives, and
// final_kernel assembles loss_i = log(neg) + (P1/neg - P2/(2neg^2) - S)/C.
// Pass2 AND the 68MB sim cache are deleted.
//   h = x/||x||  (stored fp16); s = h*h^T via single fp16 mma.sync, fp32 accum
// Symmetric: tiles bj >= bi only; off-diag tiles feed row and col accumulators.

#define NMAX 8192
#define D    256
#define INV_T 14.285714285714285714f

__device__ uint4 g_h4[NMAX * D * 2 / 16];      // fp16 [NMAX][D]
__device__ float g_neg[NMAX];
__device__ float g_P1[NMAX];
__device__ float g_P2[NMAX];
__device__ float g_S [NMAX];
__device__ float g_C [NMAX];
__device__ int   g_lab[NMAX];

// ---------------- PTX helpers (sm_80-era, valid on plain sm_103) ------------
__device__ __forceinline__ uint32_t smem_u32(const void* p) {
    uint32_t a;
    asm("{ .reg .u64 t; cvta.to.shared.u64 t, %1; cvt.u32.u64 %0, t; }" : "=r"(a) : "l"(p));
    return a;
}

#define CP_ASYNC16(dst, src) \
    asm volatile("cp.async.cg.shared.global [%0], [%1], 16;" :: "r"(dst), "l"(src) : "memory")
#define CP_COMMIT() asm volatile("cp.async.commit_group;" ::: "memory")
#define CP_WAIT0()  asm volatile("cp.async.wait_group 0;" ::: "memory")

#define LDSM_X4(r0,r1,r2,r3,addr) \
    asm volatile("ldmatrix.sync.aligned.m8n8.x4.shared.b16 {%0,%1,%2,%3}, [%4];" \
        : "=r"(r0),"=r"(r1),"=r"(r2),"=r"(r3) : "r"(addr))
#define LDSM_X2(r0,r1,addr) \
    asm volatile("ldmatrix.sync.aligned.m8n8.x2.shared.b16 {%0,%1}, [%2];" \
        : "=r"(r0),"=r"(r1) : "r"(addr))
#define MMAF16(d,a0,a1,a2,a3,b0,b1) \
    asm volatile("mma.sync.aligned.m16n8k16.row.col.f32.f16.f16.f32 " \
        "{%0,%1,%2,%3}, {%4,%5,%6,%7}, {%8,%9}, {%0,%1,%2,%3};" \
        : "+f"((d)[0]),"+f"((d)[1]),"+f"((d)[2]),"+f"((d)[3]) \
        : "r"(a0),"r"(a1),"r"(a2),"r"(a3),"r"(b0),"r"(b1))

// -------------------- dynamic SMEM layout (bytes) ---------------------------
#define SM_LABA   0        // int[128]
#define SM_LABB   512
// staging accumulators: 10 x float[128]
#define SM_SNEGR  1024
#define SM_SP1R   1536
#define SM_SP2R   2048
#define SM_SSR    2560
#define SM_SCR    3072
#define SM_SNEGC  3584
#define SM_SP1C   4096
#define SM_SP2C   4608
#define SM_SSC    5120
#define SM_SCC    5632
#define SM_TILE   6144
#define TSTRIDE   144      // 128B data + 16B pad -> ldmatrix phase covers all 32 banks
#define TBYTES    (128 * TSTRIDE)        // 18432
#define STAGE     (2 * TBYTES)           // 36864 per stage (A|B)
#define SMEM_TOTAL (SM_TILE + 2 * STAGE) // 79872 -> 2 CTAs/SM

// ---------------------------------------------------------------------------
// Label ingest, robust to int32 vs int64 storage (equality-only semantics).
// ---------------------------------------------------------------------------
__global__ void lab_kernel(const unsigned int* __restrict__ v, int N)
{
    __shared__ int s_or[1024];
    int tid = threadIdx.x;
    unsigned int o = 0;
    for (int i = 2 * tid + 1; i < N; i += 2048) o |= v[i];
    s_or[tid] = (o != 0);
    __syncthreads();
    for (int s = 512; s; s >>= 1) { if (tid < s) s_or[tid] |= s_or[tid + s]; __syncthreads(); }
    int is32 = s_or[0];
    for (int i = tid; i < N; i += 1024)
        g_lab[i] = is32 ? (int)v[i] : (int)v[2 * i];
}

// ---------------------------------------------------------------------------
// Normalize + fp16 convert. 256 threads = 8 warps, one warp per row.
// ---------------------------------------------------------------------------
__global__ __launch_bounds__(256) void prep_kernel(const float* __restrict__ x, int N)
{
    int row  = blockIdx.x * 8 + (threadIdx.x >> 5);
    if (row >= N) return;
    int lane = threadIdx.x & 31;

    const float4* x4 = reinterpret_cast<const float4*>(x + (size_t)row * D);
    float4 a = x4[lane];
    float4 b = x4[lane + 32];

    float ss = a.x*a.x + a.y*a.y + a.z*a.z + a.w*a.w
             + b.x*b.x + b.y*b.y + b.z*b.z + b.w*b.w;
#pragma unroll
    for (int o = 16; o; o >>= 1) ss += __shfl_xor_sync(0xffffffffu, ss, o);

    float inv = 1.0f / fmaxf(sqrtf(ss), 1e-12f);
    a.x *= inv; a.y *= inv; a.z *= inv; a.w *= inv;
    b.x *= inv; b.y *= inv; b.z *= inv; b.w *= inv;

    __half2* h2 = reinterpret_cast<__half2*>(g_h4);
    size_t base = (size_t)row * (D / 2);

    h2[base + lane*2 + 0]      = __floats2half2_rn(a.x, a.y);
    h2[base + lane*2 + 1]      = __floats2half2_rn(a.z, a.w);
    h2[base + 64 + lane*2 + 0] = __floats2half2_rn(b.x, b.y);
    h2[base + 64 + lane*2 + 1] = __floats2half2_rn(b.z, b.w);

    if (lane == 0) {
        g_neg[row] = 0.0f; g_P1[row] = 0.0f; g_P2[row] = 0.0f;
        g_S[row] = 0.0f;   g_C[row] = 0.0f;
    }
}

// Issue the 8 cp.async ops that fill one stage with chunk kc's two tiles.
__device__ __forceinline__ void issue_stage(uint32_t smb, int stage, int kc,
                                            int i0, int j0, int tid,
                                            const char* h_base)
{
    uint32_t sbase = smb + SM_TILE + stage * STAGE;
#pragma unroll
    for (int t = 0; t < 8; t++) {
        int idx = tid + t * 256;
        int mat = idx >> 10;          // 0 = A (rows i0), 1 = B (rows j0)
        int rem = idx & 1023;
        int row = rem >> 3;
        int c   = rem & 7;
        int grow = mat ? (j0 + row) : (i0 + row);
        const char* src = h_base + (size_t)grow * 512 + kc * 128 + c * 16;
        uint32_t dst = sbase + mat * TBYTES + row * TSTRIDE + c * 16;
        CP_ASYNC16(dst, src);
    }
    CP_COMMIT();
}

// ---------------------------------------------------------------------------
// Fused pass: fp16 GEMM (128x128 tile) + moment epilogue. 8 warps, warp tile
// 64x32; cp.async 2-stage pipeline; 2 CTAs/SM. Row accumulators flushed per
// fm (each fm feeds exactly 2 rows) to bound register pressure.
// ---------------------------------------------------------------------------
__global__ __launch_bounds__(256, 2) void pass1_kernel(int N)
{
    extern __shared__ char sm[];
    int bi = blockIdx.y, bj = blockIdx.x;
    if (bj < bi) return;

    int tid  = threadIdx.x;
    int wid  = tid >> 5;
    int lane = tid & 31;
    int i0 = bi * 128, j0 = bj * 128;
    bool offdiag = (bi != bj);
    uint32_t smb = smem_u32(sm);

    int* labA = (int*)(sm + SM_LABA);
    int* labB = (int*)(sm + SM_LABB);

    const char* h_base = (const char*)g_h4;

    issue_stage(smb, 0, 0, i0, j0, tid, h_base);

    if (tid < 128) {
        labA[tid] = g_lab[i0 + tid];
        labB[tid] = g_lab[j0 + tid];
        ((float*)(sm + SM_SNEGR))[tid] = 0.0f;
        ((float*)(sm + SM_SP1R ))[tid] = 0.0f;
        ((float*)(sm + SM_SP2R ))[tid] = 0.0f;
        ((float*)(sm + SM_SSR  ))[tid] = 0.0f;
        ((float*)(sm + SM_SCR  ))[tid] = 0.0f;
        ((float*)(sm + SM_SNEGC))[tid] = 0.0f;
        ((float*)(sm + SM_SP1C ))[tid] = 0.0f;
        ((float*)(sm + SM_SP2C ))[tid] = 0.0f;
        ((float*)(sm + SM_SSC  ))[tid] = 0.0f;
        ((float*)(sm + SM_SCC  ))[tid] = 0.0f;
    }

    int wm0 = (wid & 1) * 64;
    int wn0 = (wid >> 1) * 32;

    float acc[4][4][4];
#pragma unroll
    for (int fm = 0; fm < 4; fm++)
#pragma unroll
        for (int fn = 0; fn < 4; fn++)
#pragma unroll
            for (int k = 0; k < 4; k++) acc[fm][fn][k] = 0.0f;

    int a_row = lane & 15;
    int a_kb  = (lane >> 4) * 16;
    int b_row = lane & 7;
    int b_kb  = ((lane >> 3) & 1) * 16;

#pragma unroll
    for (int kc = 0; kc < 4; kc++) {
        int s = kc & 1;
        CP_WAIT0();
        __syncthreads();
        if (kc < 3)
            issue_stage(smb, s ^ 1, kc + 1, i0, j0, tid, h_base);

        uint32_t off_a = SM_TILE + s * STAGE;
#pragma unroll
        for (int ks = 0; ks < 4; ks++) {
            uint32_t af[4][4], bf[4][2];
#pragma unroll
            for (int fm = 0; fm < 4; fm++) {
                uint32_t ra = smb + off_a + (wm0 + fm*16 + a_row) * TSTRIDE + ks*32 + a_kb;
                LDSM_X4(af[fm][0], af[fm][1], af[fm][2], af[fm][3], ra);
            }
#pragma unroll
            for (int fn = 0; fn < 4; fn++) {
                uint32_t rb = smb + off_a + TBYTES + (wn0 + fn*8 + b_row) * TSTRIDE + ks*32 + b_kb;
                LDSM_X2(bf[fn][0], bf[fn][1], rb);
            }
#pragma unroll
            for (int fm = 0; fm < 4; fm++)
#pragma unroll
                for (int fn = 0; fn < 4; fn++)
                    MMAF16(acc[fm][fn], af[fm][0],af[fm][1],af[fm][2],af[fm][3],
                           bf[fn][0], bf[fn][1]);
        }
        __syncthreads();
    }

    // ---- fused epilogue: one exp per element feeds neg-sum AND moments ----
    int g  = lane >> 2;
    int tg = lane & 3;
    bool diag = (bi == bj);

    int la8[8], lb8[8];
#pragma unroll
    for (int fm = 0; fm < 4; fm++)
#pragma unroll
        for (int h = 0; h < 2; h++)
            la8[fm*2+h] = labA[wm0 + fm*16 + g + h*8];
#pragma unroll
    for (int fn = 0; fn < 4; fn++)
#pragma unroll
        for (int p = 0; p < 2; p++)
            lb8[fn*2+p] = labB[wn0 + fn*8 + tg*2 + p];

    // col-side accumulators persist across fm
    float cNeg[8] = {0,0,0,0,0,0,0,0};
    float cP1[8]  = {0,0,0,0,0,0,0,0};
    float cP2[8]  = {0,0,0,0,0,0,0,0};
    float cS[8]   = {0,0,0,0,0,0,0,0};
    float cC[8]   = {0,0,0,0,0,0,0,0};

#pragma unroll
    for (int fm = 0; fm < 4; fm++) {
        // row-side accumulators: this fm feeds exactly rows h=0,1
        float rNeg[2] = {0,0}, rP1[2] = {0,0}, rP2[2] = {0,0};
        float rS[2] = {0,0}, rC[2] = {0,0};
#pragma unroll
        for (int fn = 0; fn < 4; fn++)
#pragma unroll
            for (int k = 0; k < 4; k++) {
                int h = k >> 1, p = k & 1;
                int ci = fn*2 + p;
                float sT = acc[fm][fn][k] * INV_T;
                float es = __expf(sT);
                bool same = (la8[fm*2+h] == lb8[ci]);
                // diag element: same row/col position within diagonal tile
                bool de = diag && ((wm0 + fm*16 + g + h*8) == (wn0 + fn*8 + tg*2 + p));
                if (!same) {
                    rNeg[h] += es;
                    cNeg[ci] += es;
                } else if (!de) {
                    rP1[h] += es;  rP2[h] = fmaf(es, es, rP2[h]);
                    rS[h] += sT;   rC[h] += 1.0f;
                    cP1[ci] += es; cP2[ci] = fmaf(es, es, cP2[ci]);
                    cS[ci] += sT;  cC[ci] += 1.0f;
                }
            }
        // flush rows for this fm: reduce across tg (xor 1,2), atomic to smem
#pragma unroll
        for (int h = 0; h < 2; h++) {
            float vN = rNeg[h], v1 = rP1[h], v2 = rP2[h], vS = rS[h], vC = rC[h];
#pragma unroll
            for (int o = 1; o <= 2; o <<= 1) {
                vN += __shfl_xor_sync(0xffffffffu, vN, o);
                v1 += __shfl_xor_sync(0xffffffffu, v1, o);
                v2 += __shfl_xor_sync(0xffffffffu, v2, o);
                vS += __shfl_xor_sync(0xffffffffu, vS, o);
                vC += __shfl_xor_sync(0xffffffffu, vC, o);
            }
            if (tg == 0) {
                int r = wm0 + fm*16 + g + h*8;
                atomicAdd((float*)(sm + SM_SNEGR) + r, vN);
                atomicAdd((float*)(sm + SM_SP1R ) + r, v1);
                atomicAdd((float*)(sm + SM_SP2R ) + r, v2);
                atomicAdd((float*)(sm + SM_SSR  ) + r, vS);
                atomicAdd((float*)(sm + SM_SCR  ) + r, vC);
            }
        }
    }

    // flush cols: reduce across g (xor 4,8,16), atomic to smem
#pragma unroll
    for (int ci = 0; ci < 8; ci++) {
        float vN = cNeg[ci], v1 = cP1[ci], v2 = cP2[ci], vS = cS[ci], vC = cC[ci];
#pragma unroll
        for (int o = 4; o <= 16; o <<= 1) {
            vN += __shfl_xor_sync(0xffffffffu, vN, o);
            v1 += __shfl_xor_sync(0xffffffffu, v1, o);
            v2 += __shfl_xor_sync(0xffffffffu, v2, o);
            vS += __shfl_xor_sync(0xffffffffu, vS, o);
            vC += __shfl_xor_sync(0xffffffffu, vC, o);
        }
        if (g == 0) {
            int c = wn0 + (ci >> 1)*8 + tg*2 + (ci & 1);
            atomicAdd((float*)(sm + SM_SNEGC) + c, vN);
            atomicAdd((float*)(sm + SM_SP1C ) + c, v1);
            atomicAdd((float*)(sm + SM_SP2C ) + c, v2);
            atomicAdd((float*)(sm + SM_SSC  ) + c, vS);
            atomicAdd((float*)(sm + SM_SCC  ) + c, vC);
        }
    }
    __syncthreads();

    if (tid < 128) {
        atomicAdd(&g_neg[i0 + tid], ((float*)(sm + SM_SNEGR))[tid]);
        atomicAdd(&g_P1 [i0 + tid], ((float*)(sm + SM_SP1R ))[tid]);
        atomicAdd(&g_P2 [i0 + tid], ((float*)(sm + SM_SP2R ))[tid]);
        atomicAdd(&g_S  [i0 + tid], ((float*)(sm + SM_SSR  ))[tid]);
        atomicAdd(&g_C  [i0 + tid], ((float*)(sm + SM_SCR  ))[tid]);
        if (offdiag) {
            atomicAdd(&g_neg[j0 + tid], ((float*)(sm + SM_SNEGC))[tid]);
            atomicAdd(&g_P1 [j0 + tid], ((float*)(sm + SM_SP1C ))[tid]);
            atomicAdd(&g_P2 [j0 + tid], ((float*)(sm + SM_SP2C ))[tid]);
            atomicAdd(&g_S  [j0 + tid], ((float*)(sm + SM_SSC  ))[tid]);
            atomicAdd(&g_C  [j0 + tid], ((float*)(sm + SM_SCC  ))[tid]);
        }
    }
}

// ---------------------------------------------------------------------------
// Final: loss_i = log(neg) + (P1/neg - P2/(2 neg^2) - S)/C for rows with C>0.
// ---------------------------------------------------------------------------
__global__ void final_kernel(float* __restrict__ out, int N)
{
    __shared__ float sred[1024];
    __shared__ int   ired[1024];
    int tid = threadIdx.x;

    float sum = 0.0f; int vc = 0;
    for (int i = tid; i < N; i += 1024) {
        float c = g_C[i];
        if (c > 0.5f) {
            float neg = g_neg[i];
            float loss;
            if (neg > 0.0f) {
                float rn = 1.0f / neg;
                loss = logf(neg)
                     + (g_P1[i]*rn - 0.5f*g_P2[i]*rn*rn - g_S[i]) / c;
            } else {
                loss = 0.0f;   // no negatives: pair_loss == 0 exactly
            }
            sum += loss;
            vc++;
        }
    }
    sred[tid] = sum; ired[tid] = vc;
    __syncthreads();
    for (int s = 512; s; s >>= 1) {
        if (tid < s) { sred[tid] += sred[tid + s]; ired[tid] += ired[tid + s]; }
        __syncthreads();
    }
    if (tid == 0) out[0] = (ired[0] > 0) ? sred[0] / (float)ired[0] : 0.0f;
}

// ---------------------------------------------------------------------------
extern "C" void kernel_launch(void* const* d_in, const int* in_sizes, int n_in,
                              void* d_out, int out_size)
{
    const float*        x   = (const float*)d_in[0];
    const unsigned int* lv  = (const unsigned int*)d_in[1];
    float*              out = (float*)d_out;

    int N = in_sizes[1];
    if (N > NMAX) N = NMAX;

    cudaFuncSetAttribute(pass1_kernel, cudaFuncAttributeMaxDynamicSharedMemorySize, SMEM_TOTAL);

    lab_kernel<<<1, 1024>>>(lv, N);
    prep_kernel<<<(N + 7) / 8, 256>>>(x, N);

    int T = N / 128;
    dim3 grid(T, T);
    pass1_kernel<<<grid, 256, SMEM_TOTAL>>>(N);

    final_kernel<<<1, 1024>>>(out, N);
}